// round 10
// baseline (speedup 1.0000x reference)
#include <cuda_runtime.h>
#include <cuda_bf16.h>
#include <cstdint>
#include <cstddef>

#define BQ 64
#define TQ 512
#define DQ 1024
#define HQ 1024
#define ZN 4096   // 4H
#define NCTA 128  // scan CTAs; CTA j owns h cols [8j, 8j+8)

// ---------------- scratch (allocation-free __device__ globals) ----------------
__device__ float g_xz[(size_t)BQ * TQ * ZN];          // 512 MB: x @ Wi + b
// h in MMA A-fragment order, bf16 split, double-buffered by step parity:
// [buf][k16-chunk 0..63][m-tile 0..3][lane] = uint4 (a0,a1,a2,a3)
__device__ uint4 g_hfH[2][64][4][32];
__device__ uint4 g_hfL[2][64][4][32];
__device__ int   g_flag[NCTA];
__device__ int   g_done[8];                            // phase-1 t-chunk completion

// ---------------- helpers ----------------
__device__ __forceinline__ void bsplit(float v, uint16_t& h, uint16_t& l) {
    __nv_bfloat16 bh = __float2bfloat16(v);
    __nv_bfloat16 bl = __float2bfloat16(v - __bfloat162float(bh));
    h = __bfloat16_as_ushort(bh);
    l = __bfloat16_as_ushort(bl);
}
__device__ __forceinline__ void pack2(float v0, float v1, uint32_t& hi, uint32_t& lo) {
    uint16_t h0, l0, h1, l1;
    bsplit(v0, h0, l0); bsplit(v1, h1, l1);
    hi = (uint32_t)h0 | ((uint32_t)h1 << 16);
    lo = (uint32_t)l0 | ((uint32_t)l1 << 16);
}
__device__ __forceinline__ void mma16816(float c[4], uint32_t a0, uint32_t a1,
                                         uint32_t a2, uint32_t a3,
                                         uint32_t b0, uint32_t b1) {
    asm volatile(
        "mma.sync.aligned.m16n8k16.row.col.f32.bf16.bf16.f32 "
        "{%0,%1,%2,%3},{%4,%5,%6,%7},{%8,%9},{%0,%1,%2,%3};"
        : "+f"(c[0]), "+f"(c[1]), "+f"(c[2]), "+f"(c[3])
        : "r"(a0), "r"(a1), "r"(a2), "r"(a3), "r"(b0), "r"(b1));
}
__device__ __forceinline__ uint4 ldg_cg_v4(const uint4* p) {
    uint4 v;
    asm volatile("ld.global.cg.v4.b32 {%0,%1,%2,%3},[%4];"
                 : "=r"(v.x), "=r"(v.y), "=r"(v.z), "=r"(v.w) : "l"(p));
    return v;
}
__device__ __forceinline__ int ld_acq(const int* p) {
    int v;
    asm volatile("ld.global.acquire.gpu.b32 %0,[%1];" : "=r"(v) : "l"(p) : "memory");
    return v;
}
__device__ __forceinline__ void st_rel(int* p, int v) {
    asm volatile("st.global.release.gpu.b32 [%0],%1;" :: "l"(p), "r"(v) : "memory");
}
// 1-MUFU approx sigmoid (abs err ~2.4e-4): 0.5 + 0.5*tanh.approx(x/2)
__device__ __forceinline__ float sig_fast(float x) {
    float y;
    asm("tanh.approx.f32 %0,%1;" : "=f"(y) : "f"(0.5f * x));
    return fmaf(0.5f, y, 0.5f);
}
// 2-MUFU accurate tanh (~1e-6): 2/(1+e^{-2x}) - 1
__device__ __forceinline__ float tanh_acc(float x) {
    float e = __expf(-2.0f * x);
    return __fdividef(2.0f, 1.0f + e) - 1.0f;
}

// ---------------- init: h0 -> frag buffer 0, reset flags/counters ----------------
__global__ __launch_bounds__(256) void init_kernel(const float* __restrict__ h0) {
    int u = blockIdx.x * 256 + threadIdx.x;          // 8192 = 64*4*32
    if (u < NCTA) g_flag[u] = 0;
    if (u < 8)    g_done[u] = 0;
    int lane = u & 31, mt = (u >> 5) & 3, kk = u >> 7;
    int grp = lane >> 2, tig = lane & 3;
    int r0 = mt * 16 + grp, r1 = r0 + 8;
    int k0 = kk * 16 + 2 * tig;
    float2 v00 = *(const float2*)&h0[(size_t)r0 * HQ + k0];
    float2 v10 = *(const float2*)&h0[(size_t)r1 * HQ + k0];
    float2 v01 = *(const float2*)&h0[(size_t)r0 * HQ + k0 + 8];
    float2 v11 = *(const float2*)&h0[(size_t)r1 * HQ + k0 + 8];
    uint4 H, L;
    pack2(v00.x, v00.y, H.x, L.x);
    pack2(v10.x, v10.y, H.y, L.y);
    pack2(v01.x, v01.y, H.z, L.z);
    pack2(v11.x, v11.y, H.w, L.w);
    g_hfH[0][kk][mt][lane] = H;
    g_hfL[0][kk][mt][lane] = L;
}

// ---------------- phase 1: xz = x @ Wi + b  (M=32768,N=4096,K=1024) ----------------
// 1-D grid ordered by t-chunk: id = tc*2048 + b*32 + n. CTA tile 64x128, BK=32.
__global__ __launch_bounds__(256, 2) void gemm_split_kernel(
    const float* __restrict__ A, const float* __restrict__ Bm,
    const float* __restrict__ bias, float* __restrict__ C, int N, int K)
{
    __shared__ uint32_t AsH[64][20], AsL[64][20];
    __shared__ uint32_t BsH[16][136], BsL[16][136];

    const int tid  = threadIdx.x;
    const int lane = tid & 31, warp = tid >> 5;
    const int grp = lane >> 2, tig = lane & 3;
    const int wr = (warp >> 2) << 5;
    const int wc = (warp & 3) << 5;

    const int id  = blockIdx.x;
    const int tc  = id >> 11;            // t-chunk 0..7
    const int rem = id & 2047;
    const int bb  = rem >> 5, nn = rem & 31;
    const int mbase = (bb * 8 + tc) * 64;
    const int nbase = nn * 128;

    float acc[2][4][4];
    #pragma unroll
    for (int i = 0; i < 2; i++)
        #pragma unroll
        for (int j = 0; j < 4; j++)
            #pragma unroll
            for (int q = 0; q < 4; q++) acc[i][j][q] = 0.f;

    for (int k0 = 0; k0 < K; k0 += 32) {
        #pragma unroll
        for (int i = 0; i < 2; i++) {
            int idx = tid + i * 256;
            int r = idx >> 3, q = idx & 7;
            float4 v = *reinterpret_cast<const float4*>(&A[(size_t)(mbase + r) * K + k0 + q * 4]);
            pack2(v.x, v.y, AsH[r][q * 2],     AsL[r][q * 2]);
            pack2(v.z, v.w, AsH[r][q * 2 + 1], AsL[r][q * 2 + 1]);
        }
        #pragma unroll
        for (int i = 0; i < 2; i++) {
            int idx = tid + i * 256;
            int p = idx >> 5, ng = idx & 31;
            const float4 r0 = *reinterpret_cast<const float4*>(&Bm[(size_t)(k0 + 2 * p) * N + nbase + ng * 4]);
            const float4 r1 = *reinterpret_cast<const float4*>(&Bm[(size_t)(k0 + 2 * p + 1) * N + nbase + ng * 4]);
            pack2(r0.x, r1.x, BsH[p][ng * 4 + 0], BsL[p][ng * 4 + 0]);
            pack2(r0.y, r1.y, BsH[p][ng * 4 + 1], BsL[p][ng * 4 + 1]);
            pack2(r0.z, r1.z, BsH[p][ng * 4 + 2], BsL[p][ng * 4 + 2]);
            pack2(r0.w, r1.w, BsH[p][ng * 4 + 3], BsL[p][ng * 4 + 3]);
        }
        __syncthreads();

        #pragma unroll
        for (int kk = 0; kk < 2; kk++) {
            uint32_t aH[2][4], aL[2][4], bH[4][2], bL[4][2];
            #pragma unroll
            for (int mi = 0; mi < 2; mi++) {
                int r0 = wr + mi * 16 + grp, r1 = r0 + 8;
                int pq = kk * 8 + tig;
                aH[mi][0] = AsH[r0][pq];     aL[mi][0] = AsL[r0][pq];
                aH[mi][1] = AsH[r1][pq];     aL[mi][1] = AsL[r1][pq];
                aH[mi][2] = AsH[r0][pq + 4]; aL[mi][2] = AsL[r0][pq + 4];
                aH[mi][3] = AsH[r1][pq + 4]; aL[mi][3] = AsL[r1][pq + 4];
            }
            #pragma unroll
            for (int ni = 0; ni < 4; ni++) {
                int cc = wc + ni * 8 + grp;
                int p0 = kk * 8 + tig;
                bH[ni][0] = BsH[p0][cc];     bL[ni][0] = BsL[p0][cc];
                bH[ni][1] = BsH[p0 + 4][cc]; bL[ni][1] = BsL[p0 + 4][cc];
            }
            #pragma unroll
            for (int mi = 0; mi < 2; mi++)
                #pragma unroll
                for (int ni = 0; ni < 4; ni++) {
                    float* c = acc[mi][ni];
                    mma16816(c, aH[mi][0], aH[mi][1], aH[mi][2], aH[mi][3], bH[ni][0], bH[ni][1]);
                    mma16816(c, aH[mi][0], aH[mi][1], aH[mi][2], aH[mi][3], bL[ni][0], bL[ni][1]);
                    mma16816(c, aL[mi][0], aL[mi][1], aL[mi][2], aL[mi][3], bH[ni][0], bH[ni][1]);
                }
        }
        __syncthreads();
    }

    #pragma unroll
    for (int mi = 0; mi < 2; mi++) {
        int r0 = mbase + wr + mi * 16 + grp;
        #pragma unroll
        for (int ni = 0; ni < 4; ni++) {
            int c0 = nbase + wc + ni * 8 + tig * 2;
            float2 bv = *(const float2*)&bias[c0];
            __stcs((float2*)&C[(size_t)r0 * N + c0],
                   make_float2(acc[mi][ni][0] + bv.x, acc[mi][ni][1] + bv.y));
            __stcs((float2*)&C[(size_t)(r0 + 8) * N + c0],
                   make_float2(acc[mi][ni][2] + bv.x, acc[mi][ni][3] + bv.y));
        }
    }
    __threadfence();
    __syncthreads();
    if (tid == 0) atomicAdd(&g_done[tc], 1);
}

// ---------------- persistent scan kernel ----------------
// 128 CTAs x 512 thr (16 warps). Warp (mt = wid&3, kq = wid>>2): m-tile mt,
// K-quarter kq, all 4 gate n-tiles. 4 warps/SMSP keep the tensor pipe fed.
__global__ __launch_bounds__(512, 1) void scan_kernel(
    const float* __restrict__ Wh, const float* __restrict__ c0,
    float* __restrict__ out)
{
    extern __shared__ char smem[];
    uint4*  sWh  = reinterpret_cast<uint4*>(smem);            // [64][4][32] uint4 = 128KB
    float4* zsf4 = reinterpret_cast<float4*>(smem + 131072);  // [4][512] float4 = 32KB
    float*  hs   = reinterpret_cast<float*>(smem + 131072 + 32768);  // [512]
    float*  cs   = hs + 512;                                          // [512]

    const int j = blockIdx.x, tid = threadIdx.x;
    const int lane = tid & 31, warp = tid >> 5;
    const int grp = lane >> 2, tig = lane & 3;
    const int mt = warp & 3, kq = warp >> 2;     // m-tile, K-quarter
    const int kb = kq * 16;

    // ---- one-time: Wh slice -> SMEM B-fragments ----
    for (int it = 0; it < 16; it++) {
        int slot = tid + it * 512;                   // 8192 slots
        int sl = slot & 31, nt = (slot >> 5) & 3, kk = slot >> 7;
        int sg = sl >> 2, st_ = sl & 3;
        int col = nt * 1024 + j * 8 + sg;
        int k0 = kk * 16 + 2 * st_;
        float w0 = Wh[(size_t)k0 * ZN + col];
        float w1 = Wh[(size_t)(k0 + 1) * ZN + col];
        float w8 = Wh[(size_t)(k0 + 8) * ZN + col];
        float w9 = Wh[(size_t)(k0 + 9) * ZN + col];
        uint4 v;
        pack2(w0, w1, v.x, v.z);
        pack2(w8, w9, v.y, v.w);
        sWh[(kk * 4 + nt) * 32 + sl] = v;
    }
    {
        int row = tid >> 3, col = tid & 7;
        cs[tid] = c0[(size_t)row * HQ + j * 8 + col];
    }
    __syncthreads();

    const size_t OFF_C = (size_t)BQ * TQ * HQ;
    const size_t OFF_H = OFF_C + (size_t)BQ * HQ;

    for (int s = 0; s < TQ; s++) {
        const int buf = s & 1, nbuf = buf ^ 1;
        // gate on phase-1 t-chunk availability
        if ((s & 63) == 0) {
            if (tid == 0) {
                while (ld_acq(&g_done[s >> 6]) < 2048) __nanosleep(128);
            }
            __syncthreads();
        }
        // gate on all CTAs having published h(s)
        if (s > 0) {
            if (tid < NCTA) {
                while (ld_acq(&g_flag[tid]) < s) __nanosleep(32);
            }
            __syncthreads();
        }

        // prefetch xz (DRAM, read-once streaming); consumed after the MMA loop
        float xzv[4];
        {
            int row = tid >> 3, col = tid & 7;
            const float* xp = &g_xz[((size_t)row * TQ + s) * ZN + j * 8 + col];
            xzv[0] = __ldcs(xp);
            xzv[1] = __ldcs(xp + 1024);
            xzv[2] = __ldcs(xp + 2048);
            xzv[3] = __ldcs(xp + 3072);
        }

        float acc[4][4];
        #pragma unroll
        for (int nt = 0; nt < 4; nt++)
            #pragma unroll
            for (int q = 0; q < 4; q++) acc[nt][q] = 0.f;

        // distance-2 prefetched A-frag loop over this warp's K-quarter
        uint4 A0H = ldg_cg_v4(&g_hfH[buf][kb + 0][mt][lane]);
        uint4 A0L = ldg_cg_v4(&g_hfL[buf][kb + 0][mt][lane]);
        uint4 A1H = ldg_cg_v4(&g_hfH[buf][kb + 1][mt][lane]);
        uint4 A1L = ldg_cg_v4(&g_hfL[buf][kb + 1][mt][lane]);
        #pragma unroll 4
        for (int i = 0; i < 16; i++) {
            uint4 AH = A0H, AL = A0L;
            A0H = A1H; A0L = A1L;
            if (i + 2 < 16) {
                A1H = ldg_cg_v4(&g_hfH[buf][kb + i + 2][mt][lane]);
                A1L = ldg_cg_v4(&g_hfL[buf][kb + i + 2][mt][lane]);
            }
            const int kk = kb + i;
            #pragma unroll
            for (int nt = 0; nt < 4; nt++) {
                uint4 Bv = sWh[(kk * 4 + nt) * 32 + lane];
                mma16816(acc[nt], AH.x, AH.y, AH.z, AH.w, Bv.x, Bv.y);
                mma16816(acc[nt], AH.x, AH.y, AH.z, AH.w, Bv.z, Bv.w);
                mma16816(acc[nt], AL.x, AL.y, AL.z, AL.w, Bv.x, Bv.y);
            }
        }

        // stage K-quarter partials: all 4 gates per element as one float4
        {
            #pragma unroll
            for (int q = 0; q < 4; q++) {
                int row = mt * 16 + grp + ((q >> 1) << 3);
                int col = 2 * tig + (q & 1);
                zsf4[kq * 512 + row * 8 + col] =
                    make_float4(acc[0][q], acc[1][q], acc[2][q], acc[3][q]);
            }
        }
        __syncthreads();

        // gates + state update (reduce the four K-quarter partials); 1 elem/thread
        {
            int row = tid >> 3, col = tid & 7;
            float4 z = zsf4[tid];
            #pragma unroll
            for (int kz = 1; kz < 4; kz++) {
                float4 p = zsf4[kz * 512 + tid];
                z.x += p.x; z.y += p.y; z.z += p.z; z.w += p.w;
            }
            float zi = z.x + xzv[0];
            float zf = z.y + xzv[1];
            float zg = z.z + xzv[2];
            float zo = z.w + xzv[3];
            float c  = cs[tid];
            float nc = sig_fast(zf) * c + sig_fast(zi) * tanh_acc(zg);
            float nh = sig_fast(zo) * tanh_acc(nc);
            cs[tid] = nc;
            hs[tid] = nh;
            __stcs(&out[((size_t)row * TQ + s) * HQ + j * 8 + col], nh);
            if (s == TQ - 1) {
                __stcs(&out[OFF_C + (size_t)row * HQ + j * 8 + col], nc);
                __stcs(&out[OFF_H + (size_t)row * HQ + j * 8 + col], nh);
            }
        }
        __syncthreads();

        // publish new h as A-fragments into buffer nbuf (128 publisher threads)
        if (tid < 128) {
            int mt2 = tid >> 5, ln = tid & 31;
            int g2 = ln >> 2, t2 = ln & 3;
            int r0 = mt2 * 16 + g2, r1 = r0 + 8, cc = 2 * t2;
            uint2 H, L;
            pack2(hs[r0 * 8 + cc], hs[r0 * 8 + cc + 1], H.x, L.x);
            pack2(hs[r1 * 8 + cc], hs[r1 * 8 + cc + 1], H.y, L.y);
            uint2* dH = reinterpret_cast<uint2*>(&g_hfH[nbuf][j >> 1][mt2][ln]);
            uint2* dL = reinterpret_cast<uint2*>(&g_hfL[nbuf][j >> 1][mt2][ln]);
            dH[j & 1] = H;
            dL[j & 1] = L;
        }
        // release pattern: barrier gives intra-CTA happens-before for the frag
        // stores; tid0's release store then publishes them to acquiring CTAs.
        __syncthreads();
        if (tid == 0) st_rel(&g_flag[j], s + 1);
    }
}

// ---------------- launch: forked capture, phase1 overlaps the scan ----------------
extern "C" void kernel_launch(void* const* d_in, const int* in_sizes, int n_in,
                              void* d_out, int out_size)
{
    (void)in_sizes; (void)n_in; (void)out_size;
    const float* x  = (const float*)d_in[0];
    const float* h0 = (const float*)d_in[1];
    const float* c0 = (const float*)d_in[2];
    const float* Wi = (const float*)d_in[3];
    const float* Wh = (const float*)d_in[4];
    const float* b  = (const float*)d_in[5];
    float* out = (float*)d_out;

    float* xz_p = nullptr;
    cudaGetSymbolAddress((void**)&xz_p, g_xz);

    const int SCAN_SMEM = 131072 + 32768 + 2048 + 2048;   // 167936

    static cudaStream_t s2 = nullptr;
    static cudaEvent_t evA = nullptr, evB = nullptr;
    static bool inited = false;
    if (!inited) {
        cudaStreamCreateWithFlags(&s2, cudaStreamNonBlocking);
        cudaEventCreateWithFlags(&evA, cudaEventDisableTiming);
        cudaEventCreateWithFlags(&evB, cudaEventDisableTiming);
        cudaFuncSetAttribute(scan_kernel, cudaFuncAttributeMaxDynamicSharedMemorySize, SCAN_SMEM);
        inited = true;
    }

    init_kernel<<<32, 256>>>(h0);

    // fork: phase-1 GEMM on s2, ordered after init
    cudaEventRecord(evA, 0);
    cudaStreamWaitEvent(s2, evA, 0);
    gemm_split_kernel<<<16384, 256, 0, s2>>>(x, Wi, b, xz_p, ZN, DQ);
    cudaEventRecord(evB, s2);

    // scan runs concurrently on the main stream; chunk-gated on g_done
    scan_kernel<<<NCTA, 512, SCAN_SMEM>>>(Wh, c0, out);

    // join
    cudaStreamWaitEvent(0, evB, 0);
}

// round 11
// speedup vs baseline: 1.2318x; 1.2318x over previous
#include <cuda_runtime.h>
#include <cuda_bf16.h>
#include <cstdint>
#include <cstddef>

#define BQ 64
#define TQ 512
#define DQ 1024
#define HQ 1024
#define ZN 4096   // 4H
#define NCTA 128  // scan CTAs; CTA j owns h cols [8j, 8j+8)

// ---------------- scratch (allocation-free __device__ globals) ----------------
__device__ float g_xz[(size_t)BQ * TQ * ZN];          // 512 MB: x @ Wi + b
// h in MMA A-fragment order, bf16 split, double-buffered by step parity:
// [buf][k16-chunk 0..63][m-tile 0..3][lane] = uint4 (a0,a1,a2,a3)
__device__ uint4 g_hfH[2][64][4][32];
__device__ uint4 g_hfL[2][64][4][32];
__device__ int   g_flag[NCTA];
__device__ int   g_done[8];                            // phase-1 t-chunk completion

// ---------------- helpers ----------------
__device__ __forceinline__ void bsplit(float v, uint16_t& h, uint16_t& l) {
    __nv_bfloat16 bh = __float2bfloat16(v);
    __nv_bfloat16 bl = __float2bfloat16(v - __bfloat162float(bh));
    h = __bfloat16_as_ushort(bh);
    l = __bfloat16_as_ushort(bl);
}
__device__ __forceinline__ void pack2(float v0, float v1, uint32_t& hi, uint32_t& lo) {
    uint16_t h0, l0, h1, l1;
    bsplit(v0, h0, l0); bsplit(v1, h1, l1);
    hi = (uint32_t)h0 | ((uint32_t)h1 << 16);
    lo = (uint32_t)l0 | ((uint32_t)l1 << 16);
}
__device__ __forceinline__ void mma16816(float c[4], uint32_t a0, uint32_t a1,
                                         uint32_t a2, uint32_t a3,
                                         uint32_t b0, uint32_t b1) {
    asm volatile(
        "mma.sync.aligned.m16n8k16.row.col.f32.bf16.bf16.f32 "
        "{%0,%1,%2,%3},{%4,%5,%6,%7},{%8,%9},{%0,%1,%2,%3};"
        : "+f"(c[0]), "+f"(c[1]), "+f"(c[2]), "+f"(c[3])
        : "r"(a0), "r"(a1), "r"(a2), "r"(a3), "r"(b0), "r"(b1));
}
__device__ __forceinline__ uint4 ldg_cg_v4(const uint4* p) {
    uint4 v;
    asm volatile("ld.global.cg.v4.b32 {%0,%1,%2,%3},[%4];"
                 : "=r"(v.x), "=r"(v.y), "=r"(v.z), "=r"(v.w) : "l"(p));
    return v;
}
__device__ __forceinline__ int ld_acq(const int* p) {
    int v;
    asm volatile("ld.global.acquire.gpu.b32 %0,[%1];" : "=r"(v) : "l"(p) : "memory");
    return v;
}
// 1-MUFU approx sigmoid (abs err ~2.4e-4): 0.5 + 0.5*tanh.approx(x/2)
__device__ __forceinline__ float sig_fast(float x) {
    float y;
    asm("tanh.approx.f32 %0,%1;" : "=f"(y) : "f"(0.5f * x));
    return fmaf(0.5f, y, 0.5f);
}
// 2-MUFU accurate tanh (~1e-6): 2/(1+e^{-2x}) - 1
__device__ __forceinline__ float tanh_acc(float x) {
    float e = __expf(-2.0f * x);
    return __fdividef(2.0f, 1.0f + e) - 1.0f;
}

// ---------------- init: h0 -> frag buffer 0, reset flags/counters ----------------
__global__ __launch_bounds__(256) void init_kernel(const float* __restrict__ h0) {
    int u = blockIdx.x * 256 + threadIdx.x;          // 8192 = 64*4*32
    if (u < NCTA) g_flag[u] = 0;
    if (u < 8)    g_done[u] = 0;
    int lane = u & 31, mt = (u >> 5) & 3, kk = u >> 7;
    int grp = lane >> 2, tig = lane & 3;
    int r0 = mt * 16 + grp, r1 = r0 + 8;
    int k0 = kk * 16 + 2 * tig;
    float2 v00 = *(const float2*)&h0[(size_t)r0 * HQ + k0];
    float2 v10 = *(const float2*)&h0[(size_t)r1 * HQ + k0];
    float2 v01 = *(const float2*)&h0[(size_t)r0 * HQ + k0 + 8];
    float2 v11 = *(const float2*)&h0[(size_t)r1 * HQ + k0 + 8];
    uint4 H, L;
    pack2(v00.x, v00.y, H.x, L.x);
    pack2(v10.x, v10.y, H.y, L.y);
    pack2(v01.x, v01.y, H.z, L.z);
    pack2(v11.x, v11.y, H.w, L.w);
    g_hfH[0][kk][mt][lane] = H;
    g_hfL[0][kk][mt][lane] = L;
}

// ---------------- phase 1: xz = x @ Wi + b  (M=32768,N=4096,K=1024) ----------------
// 1-D grid ordered by t-chunk: id = tc*2048 + b*32 + n. CTA tile 64x128, BK=32.
__global__ __launch_bounds__(256, 2) void gemm_split_kernel(
    const float* __restrict__ A, const float* __restrict__ Bm,
    const float* __restrict__ bias, float* __restrict__ C, int N, int K)
{
    __shared__ uint32_t AsH[64][20], AsL[64][20];
    __shared__ uint32_t BsH[16][136], BsL[16][136];

    const int tid  = threadIdx.x;
    const int lane = tid & 31, warp = tid >> 5;
    const int grp = lane >> 2, tig = lane & 3;
    const int wr = (warp >> 2) << 5;
    const int wc = (warp & 3) << 5;

    const int id  = blockIdx.x;
    const int tc  = id >> 11;            // t-chunk 0..7
    const int rem = id & 2047;
    const int bb  = rem >> 5, nn = rem & 31;
    const int mbase = (bb * 8 + tc) * 64;
    const int nbase = nn * 128;

    float acc[2][4][4];
    #pragma unroll
    for (int i = 0; i < 2; i++)
        #pragma unroll
        for (int j = 0; j < 4; j++)
            #pragma unroll
            for (int q = 0; q < 4; q++) acc[i][j][q] = 0.f;

    for (int k0 = 0; k0 < K; k0 += 32) {
        #pragma unroll
        for (int i = 0; i < 2; i++) {
            int idx = tid + i * 256;
            int r = idx >> 3, q = idx & 7;
            float4 v = *reinterpret_cast<const float4*>(&A[(size_t)(mbase + r) * K + k0 + q * 4]);
            pack2(v.x, v.y, AsH[r][q * 2],     AsL[r][q * 2]);
            pack2(v.z, v.w, AsH[r][q * 2 + 1], AsL[r][q * 2 + 1]);
        }
        #pragma unroll
        for (int i = 0; i < 2; i++) {
            int idx = tid + i * 256;
            int p = idx >> 5, ng = idx & 31;
            const float4 r0 = *reinterpret_cast<const float4*>(&Bm[(size_t)(k0 + 2 * p) * N + nbase + ng * 4]);
            const float4 r1 = *reinterpret_cast<const float4*>(&Bm[(size_t)(k0 + 2 * p + 1) * N + nbase + ng * 4]);
            pack2(r0.x, r1.x, BsH[p][ng * 4 + 0], BsL[p][ng * 4 + 0]);
            pack2(r0.y, r1.y, BsH[p][ng * 4 + 1], BsL[p][ng * 4 + 1]);
            pack2(r0.z, r1.z, BsH[p][ng * 4 + 2], BsL[p][ng * 4 + 2]);
            pack2(r0.w, r1.w, BsH[p][ng * 4 + 3], BsL[p][ng * 4 + 3]);
        }
        __syncthreads();

        #pragma unroll
        for (int kk = 0; kk < 2; kk++) {
            uint32_t aH[2][4], aL[2][4], bH[4][2], bL[4][2];
            #pragma unroll
            for (int mi = 0; mi < 2; mi++) {
                int r0 = wr + mi * 16 + grp, r1 = r0 + 8;
                int pq = kk * 8 + tig;
                aH[mi][0] = AsH[r0][pq];     aL[mi][0] = AsL[r0][pq];
                aH[mi][1] = AsH[r1][pq];     aL[mi][1] = AsL[r1][pq];
                aH[mi][2] = AsH[r0][pq + 4]; aL[mi][2] = AsL[r0][pq + 4];
                aH[mi][3] = AsH[r1][pq + 4]; aL[mi][3] = AsL[r1][pq + 4];
            }
            #pragma unroll
            for (int ni = 0; ni < 4; ni++) {
                int cc = wc + ni * 8 + grp;
                int p0 = kk * 8 + tig;
                bH[ni][0] = BsH[p0][cc];     bL[ni][0] = BsL[p0][cc];
                bH[ni][1] = BsH[p0 + 4][cc]; bL[ni][1] = BsL[p0 + 4][cc];
            }
            #pragma unroll
            for (int mi = 0; mi < 2; mi++)
                #pragma unroll
                for (int ni = 0; ni < 4; ni++) {
                    float* c = acc[mi][ni];
                    mma16816(c, aH[mi][0], aH[mi][1], aH[mi][2], aH[mi][3], bH[ni][0], bH[ni][1]);
                    mma16816(c, aH[mi][0], aH[mi][1], aH[mi][2], aH[mi][3], bL[ni][0], bL[ni][1]);
                    mma16816(c, aL[mi][0], aL[mi][1], aL[mi][2], aL[mi][3], bH[ni][0], bH[ni][1]);
                }
        }
        __syncthreads();
    }

    #pragma unroll
    for (int mi = 0; mi < 2; mi++) {
        int r0 = mbase + wr + mi * 16 + grp;
        #pragma unroll
        for (int ni = 0; ni < 4; ni++) {
            int c0 = nbase + wc + ni * 8 + tig * 2;
            float2 bv = *(const float2*)&bias[c0];
            __stcs((float2*)&C[(size_t)r0 * N + c0],
                   make_float2(acc[mi][ni][0] + bv.x, acc[mi][ni][1] + bv.y));
            __stcs((float2*)&C[(size_t)(r0 + 8) * N + c0],
                   make_float2(acc[mi][ni][2] + bv.x, acc[mi][ni][3] + bv.y));
        }
    }
    __threadfence();
    __syncthreads();
    if (tid == 0) atomicAdd(&g_done[tc], 1);
}

// ---------------- persistent scan kernel ----------------
// 128 CTAs x 512 thr (16 warps). Warp (mt = wid&3, kq = wid>>2): m-tile mt,
// K-quarter kq, all 4 gate n-tiles. 4 warps/SMSP keep the tensor pipe fed.
// SMEM padded to 208KB so no phase-1 CTA can co-reside on scan SMs.
__global__ __launch_bounds__(512, 1) void scan_kernel(
    const float* __restrict__ Wh, const float* __restrict__ c0,
    float* __restrict__ out)
{
    extern __shared__ char smem[];
    uint4* sWh = reinterpret_cast<uint4*>(smem);            // [64][4][32] uint4 = 128KB
    float* zsf = reinterpret_cast<float*>(smem + 131072);   // [4][4][64][8] = 32KB partials
    float* hs  = zsf + 8192;                                // [64][8]
    float* cs  = hs + 512;                                  // [64][8]

    const int j = blockIdx.x, tid = threadIdx.x;
    const int lane = tid & 31, warp = tid >> 5;
    const int grp = lane >> 2, tig = lane & 3;
    const int mt = warp & 3, kq = warp >> 2;     // m-tile, K-quarter
    const int kb = kq * 16;

    // ---- one-time: Wh slice -> SMEM B-fragments ----
    for (int it = 0; it < 16; it++) {
        int slot = tid + it * 512;                   // 8192 slots
        int sl = slot & 31, nt = (slot >> 5) & 3, kk = slot >> 7;
        int sg = sl >> 2, st_ = sl & 3;
        int col = nt * 1024 + j * 8 + sg;
        int k0 = kk * 16 + 2 * st_;
        float w0 = Wh[(size_t)k0 * ZN + col];
        float w1 = Wh[(size_t)(k0 + 1) * ZN + col];
        float w8 = Wh[(size_t)(k0 + 8) * ZN + col];
        float w9 = Wh[(size_t)(k0 + 9) * ZN + col];
        uint4 v;
        pack2(w0, w1, v.x, v.z);
        pack2(w8, w9, v.y, v.w);
        sWh[(kk * 4 + nt) * 32 + sl] = v;
    }
    {
        int row = tid >> 3, col = tid & 7;
        cs[tid] = c0[(size_t)row * HQ + j * 8 + col];
    }
    __syncthreads();

    const size_t OFF_C = (size_t)BQ * TQ * HQ;
    const size_t OFF_H = OFF_C + (size_t)BQ * HQ;

    for (int s = 0; s < TQ; s++) {
        const int buf = s & 1, nbuf = buf ^ 1;
        // gate on phase-1 t-chunk availability
        if ((s & 63) == 0) {
            if (tid == 0) {
                while (ld_acq(&g_done[s >> 6]) < 2048) __nanosleep(128);
            }
            __syncthreads();
        }
        // gate on all CTAs having published h(s)
        if (s > 0) {
            if (tid < NCTA) {
                while (ld_acq(&g_flag[tid]) < s) __nanosleep(32);
            }
            __syncthreads();
        }

        // prefetch xz (DRAM, read-once streaming); consumed after the MMA loop
        float xzv[4];
        {
            int row = tid >> 3, col = tid & 7;
            const float* xp = &g_xz[((size_t)row * TQ + s) * ZN + j * 8 + col];
            xzv[0] = __ldcs(xp);
            xzv[1] = __ldcs(xp + 1024);
            xzv[2] = __ldcs(xp + 2048);
            xzv[3] = __ldcs(xp + 3072);
        }

        float acc[4][4];
        #pragma unroll
        for (int nt = 0; nt < 4; nt++)
            #pragma unroll
            for (int q = 0; q < 4; q++) acc[nt][q] = 0.f;

        // distance-2 prefetched A-frag loop over this warp's K-quarter
        uint4 A0H = ldg_cg_v4(&g_hfH[buf][kb + 0][mt][lane]);
        uint4 A0L = ldg_cg_v4(&g_hfL[buf][kb + 0][mt][lane]);
        uint4 A1H = ldg_cg_v4(&g_hfH[buf][kb + 1][mt][lane]);
        uint4 A1L = ldg_cg_v4(&g_hfL[buf][kb + 1][mt][lane]);
        #pragma unroll 4
        for (int i = 0; i < 16; i++) {
            uint4 AH = A0H, AL = A0L;
            A0H = A1H; A0L = A1L;
            if (i + 2 < 16) {
                A1H = ldg_cg_v4(&g_hfH[buf][kb + i + 2][mt][lane]);
                A1L = ldg_cg_v4(&g_hfL[buf][kb + i + 2][mt][lane]);
            }
            const int kk = kb + i;
            #pragma unroll
            for (int nt = 0; nt < 4; nt++) {
                uint4 Bv = sWh[(kk * 4 + nt) * 32 + lane];
                mma16816(acc[nt], AH.x, AH.y, AH.z, AH.w, Bv.x, Bv.y);
                mma16816(acc[nt], AH.x, AH.y, AH.z, AH.w, Bv.z, Bv.w);
                mma16816(acc[nt], AL.x, AL.y, AL.z, AL.w, Bv.x, Bv.y);
            }
        }

        // stage K-quarter partials
        {
            int r0 = mt * 16 + grp, r1 = r0 + 8, cc = 2 * tig;
            #pragma unroll
            for (int nt = 0; nt < 4; nt++) {
                float* zb = &zsf[(kq * 4 + nt) * 512];
                *(float2*)&zb[r0 * 8 + cc] = make_float2(acc[nt][0], acc[nt][1]);
                *(float2*)&zb[r1 * 8 + cc] = make_float2(acc[nt][2], acc[nt][3]);
            }
        }
        __syncthreads();

        // gates + state update (reduce the four K-quarter partials); 1 elem/thread
        {
            int row = tid >> 3, col = tid & 7;
            int o = tid;
            float zi = (zsf[0 * 512 + o] + zsf[4 * 512 + o]) + (zsf[8 * 512 + o]  + zsf[12 * 512 + o]) + xzv[0];
            float zf = (zsf[1 * 512 + o] + zsf[5 * 512 + o]) + (zsf[9 * 512 + o]  + zsf[13 * 512 + o]) + xzv[1];
            float zg = (zsf[2 * 512 + o] + zsf[6 * 512 + o]) + (zsf[10 * 512 + o] + zsf[14 * 512 + o]) + xzv[2];
            float zo = (zsf[3 * 512 + o] + zsf[7 * 512 + o]) + (zsf[11 * 512 + o] + zsf[15 * 512 + o]) + xzv[3];
            float c  = cs[o];
            float nc = sig_fast(zf) * c + sig_fast(zi) * tanh_acc(zg);
            float nh = sig_fast(zo) * tanh_acc(nc);
            cs[o] = nc;
            hs[o] = nh;
            __stcs(&out[((size_t)row * TQ + s) * HQ + j * 8 + col], nh);
            if (s == TQ - 1) {
                __stcs(&out[OFF_C + (size_t)row * HQ + j * 8 + col], nc);
                __stcs(&out[OFF_H + (size_t)row * HQ + j * 8 + col], nh);
            }
        }
        __syncthreads();

        // publish new h as A-fragments into buffer nbuf
        if (tid < 128) {
            int mt2 = tid >> 5, ln = tid & 31;
            int g2 = ln >> 2, t2 = ln & 3;
            int r0 = mt2 * 16 + g2, r1 = r0 + 8, cc = 2 * t2;
            uint2 H, L;
            pack2(hs[r0 * 8 + cc], hs[r0 * 8 + cc + 1], H.x, L.x);
            pack2(hs[r1 * 8 + cc], hs[r1 * 8 + cc + 1], H.y, L.y);
            uint2* dH = reinterpret_cast<uint2*>(&g_hfH[nbuf][j >> 1][mt2][ln]);
            uint2* dL = reinterpret_cast<uint2*>(&g_hfL[nbuf][j >> 1][mt2][ln]);
            dH[j & 1] = H;
            dL[j & 1] = L;
        }
        __threadfence();
        __syncthreads();
        if (tid == 0) atomicExch(&g_flag[j], s + 1);
    }
}

// ---------------- launch: forked capture, phase1 overlaps the scan ----------------
extern "C" void kernel_launch(void* const* d_in, const int* in_sizes, int n_in,
                              void* d_out, int out_size)
{
    (void)in_sizes; (void)n_in; (void)out_size;
    const float* x  = (const float*)d_in[0];
    const float* h0 = (const float*)d_in[1];
    const float* c0 = (const float*)d_in[2];
    const float* Wi = (const float*)d_in[3];
    const float* Wh = (const float*)d_in[4];
    const float* b  = (const float*)d_in[5];
    float* out = (float*)d_out;

    float* xz_p = nullptr;
    cudaGetSymbolAddress((void**)&xz_p, g_xz);

    // 208 KB: used = 164 KB; padding forces phase-1 CTAs OFF the scan's SMs
    // (208 + 28 > 228 KB carveout), eliminating tensor-pipe contention.
    const int SCAN_SMEM = 212992;

    static cudaStream_t s2 = nullptr;
    static cudaEvent_t evA = nullptr, evB = nullptr;
    static bool inited = false;
    if (!inited) {
        cudaStreamCreateWithFlags(&s2, cudaStreamNonBlocking);
        cudaEventCreateWithFlags(&evA, cudaEventDisableTiming);
        cudaEventCreateWithFlags(&evB, cudaEventDisableTiming);
        cudaFuncSetAttribute(scan_kernel, cudaFuncAttributeMaxDynamicSharedMemorySize, SCAN_SMEM);
        inited = true;
    }

    init_kernel<<<32, 256>>>(h0);

    // fork: phase-1 GEMM on s2, ordered after init (runs on the ~20 free SMs)
    cudaEventRecord(evA, 0);
    cudaStreamWaitEvent(s2, evA, 0);
    gemm_split_kernel<<<16384, 256, 0, s2>>>(x, Wi, b, xz_p, ZN, DQ);
    cudaEventRecord(evB, s2);

    // scan runs concurrently on the main stream; chunk-gated on g_done
    scan_kernel<<<NCTA, 512, SCAN_SMEM>>>(Wh, c0, out);

    // join
    cudaStreamWaitEvent(0, evB, 0);
}

// round 12
// speedup vs baseline: 1.2935x; 1.0500x over previous
#include <cuda_runtime.h>
#include <cuda_bf16.h>
#include <cstdint>
#include <cstddef>

#define BQ 64
#define TQ 512
#define DQ 1024
#define HQ 1024
#define ZN 4096   // 4H
#define NCTA 128  // scan CTAs; CTA j owns h cols [8j, 8j+8)

// ---------------- scratch (allocation-free __device__ globals) ----------------
__device__ float g_xz[(size_t)BQ * TQ * ZN];          // 512 MB: x @ Wi + b
// h in MMA A-fragment order, bf16 split, double-buffered by step parity:
// [buf][k16-chunk 0..63][m-tile 0..3][lane] = uint4 (a0,a1,a2,a3)
__device__ uint4 g_hfH[2][64][4][32];
__device__ uint4 g_hfL[2][64][4][32];
__device__ int   g_flag[NCTA];
__device__ int   g_done[8];                            // phase-1 t-chunk completion

// ---------------- helpers ----------------
__device__ __forceinline__ void bsplit(float v, uint16_t& h, uint16_t& l) {
    __nv_bfloat16 bh = __float2bfloat16(v);
    __nv_bfloat16 bl = __float2bfloat16(v - __bfloat162float(bh));
    h = __bfloat16_as_ushort(bh);
    l = __bfloat16_as_ushort(bl);
}
__device__ __forceinline__ void pack2(float v0, float v1, uint32_t& hi, uint32_t& lo) {
    uint16_t h0, l0, h1, l1;
    bsplit(v0, h0, l0); bsplit(v1, h1, l1);
    hi = (uint32_t)h0 | ((uint32_t)h1 << 16);
    lo = (uint32_t)l0 | ((uint32_t)l1 << 16);
}
__device__ __forceinline__ void mma16816(float c[4], uint32_t a0, uint32_t a1,
                                         uint32_t a2, uint32_t a3,
                                         uint32_t b0, uint32_t b1) {
    asm volatile(
        "mma.sync.aligned.m16n8k16.row.col.f32.bf16.bf16.f32 "
        "{%0,%1,%2,%3},{%4,%5,%6,%7},{%8,%9},{%0,%1,%2,%3};"
        : "+f"(c[0]), "+f"(c[1]), "+f"(c[2]), "+f"(c[3])
        : "r"(a0), "r"(a1), "r"(a2), "r"(a3), "r"(b0), "r"(b1));
}
__device__ __forceinline__ uint4 ldg_cg_v4(const uint4* p) {
    uint4 v;
    asm volatile("ld.global.cg.v4.b32 {%0,%1,%2,%3},[%4];"
                 : "=r"(v.x), "=r"(v.y), "=r"(v.z), "=r"(v.w) : "l"(p));
    return v;
}
__device__ __forceinline__ int ld_acq(const int* p) {
    int v;
    asm volatile("ld.global.acquire.gpu.b32 %0,[%1];" : "=r"(v) : "l"(p) : "memory");
    return v;
}
// 1-MUFU approx sigmoid (abs err ~2.4e-4): 0.5 + 0.5*tanh.approx(x/2)
__device__ __forceinline__ float sig_fast(float x) {
    float y;
    asm("tanh.approx.f32 %0,%1;" : "=f"(y) : "f"(0.5f * x));
    return fmaf(0.5f, y, 0.5f);
}
// 2-MUFU accurate tanh (~1e-6): 2/(1+e^{-2x}) - 1
__device__ __forceinline__ float tanh_acc(float x) {
    float e = __expf(-2.0f * x);
    return __fdividef(2.0f, 1.0f + e) - 1.0f;
}

// ---------------- init: h0 -> frag buffer 0, reset flags/counters ----------------
__global__ __launch_bounds__(256) void init_kernel(const float* __restrict__ h0) {
    int u = blockIdx.x * 256 + threadIdx.x;          // 8192 = 64*4*32
    if (u < NCTA) g_flag[u] = 0;
    if (u < 8)    g_done[u] = 0;
    int lane = u & 31, mt = (u >> 5) & 3, kk = u >> 7;
    int grp = lane >> 2, tig = lane & 3;
    int r0 = mt * 16 + grp, r1 = r0 + 8;
    int k0 = kk * 16 + 2 * tig;
    float2 v00 = *(const float2*)&h0[(size_t)r0 * HQ + k0];
    float2 v10 = *(const float2*)&h0[(size_t)r1 * HQ + k0];
    float2 v01 = *(const float2*)&h0[(size_t)r0 * HQ + k0 + 8];
    float2 v11 = *(const float2*)&h0[(size_t)r1 * HQ + k0 + 8];
    uint4 H, L;
    pack2(v00.x, v00.y, H.x, L.x);
    pack2(v10.x, v10.y, H.y, L.y);
    pack2(v01.x, v01.y, H.z, L.z);
    pack2(v11.x, v11.y, H.w, L.w);
    g_hfH[0][kk][mt][lane] = H;
    g_hfL[0][kk][mt][lane] = L;
}

// ---------------- phase 1: xz = x @ Wi + b  (M=32768,N=4096,K=1024) ----------------
// 1-D grid ordered by t-chunk: id = tc*2048 + b*32 + n. CTA tile 64x128, BK=32.
__global__ __launch_bounds__(256, 2) void gemm_split_kernel(
    const float* __restrict__ A, const float* __restrict__ Bm,
    const float* __restrict__ bias, float* __restrict__ C, int N, int K)
{
    __shared__ uint32_t AsH[64][20], AsL[64][20];
    __shared__ uint32_t BsH[16][136], BsL[16][136];

    const int tid  = threadIdx.x;
    const int lane = tid & 31, warp = tid >> 5;
    const int grp = lane >> 2, tig = lane & 3;
    const int wr = (warp >> 2) << 5;
    const int wc = (warp & 3) << 5;

    const int id  = blockIdx.x;
    const int tc  = id >> 11;            // t-chunk 0..7
    const int rem = id & 2047;
    const int bb  = rem >> 5, nn = rem & 31;
    const int mbase = (bb * 8 + tc) * 64;
    const int nbase = nn * 128;

    float acc[2][4][4];
    #pragma unroll
    for (int i = 0; i < 2; i++)
        #pragma unroll
        for (int j = 0; j < 4; j++)
            #pragma unroll
            for (int q = 0; q < 4; q++) acc[i][j][q] = 0.f;

    for (int k0 = 0; k0 < K; k0 += 32) {
        #pragma unroll
        for (int i = 0; i < 2; i++) {
            int idx = tid + i * 256;
            int r = idx >> 3, q = idx & 7;
            float4 v = *reinterpret_cast<const float4*>(&A[(size_t)(mbase + r) * K + k0 + q * 4]);
            pack2(v.x, v.y, AsH[r][q * 2],     AsL[r][q * 2]);
            pack2(v.z, v.w, AsH[r][q * 2 + 1], AsL[r][q * 2 + 1]);
        }
        #pragma unroll
        for (int i = 0; i < 2; i++) {
            int idx = tid + i * 256;
            int p = idx >> 5, ng = idx & 31;
            const float4 r0 = *reinterpret_cast<const float4*>(&Bm[(size_t)(k0 + 2 * p) * N + nbase + ng * 4]);
            const float4 r1 = *reinterpret_cast<const float4*>(&Bm[(size_t)(k0 + 2 * p + 1) * N + nbase + ng * 4]);
            pack2(r0.x, r1.x, BsH[p][ng * 4 + 0], BsL[p][ng * 4 + 0]);
            pack2(r0.y, r1.y, BsH[p][ng * 4 + 1], BsL[p][ng * 4 + 1]);
            pack2(r0.z, r1.z, BsH[p][ng * 4 + 2], BsL[p][ng * 4 + 2]);
            pack2(r0.w, r1.w, BsH[p][ng * 4 + 3], BsL[p][ng * 4 + 3]);
        }
        __syncthreads();

        #pragma unroll
        for (int kk = 0; kk < 2; kk++) {
            uint32_t aH[2][4], aL[2][4], bH[4][2], bL[4][2];
            #pragma unroll
            for (int mi = 0; mi < 2; mi++) {
                int r0 = wr + mi * 16 + grp, r1 = r0 + 8;
                int pq = kk * 8 + tig;
                aH[mi][0] = AsH[r0][pq];     aL[mi][0] = AsL[r0][pq];
                aH[mi][1] = AsH[r1][pq];     aL[mi][1] = AsL[r1][pq];
                aH[mi][2] = AsH[r0][pq + 4]; aL[mi][2] = AsL[r0][pq + 4];
                aH[mi][3] = AsH[r1][pq + 4]; aL[mi][3] = AsL[r1][pq + 4];
            }
            #pragma unroll
            for (int ni = 0; ni < 4; ni++) {
                int cc = wc + ni * 8 + grp;
                int p0 = kk * 8 + tig;
                bH[ni][0] = BsH[p0][cc];     bL[ni][0] = BsL[p0][cc];
                bH[ni][1] = BsH[p0 + 4][cc]; bL[ni][1] = BsL[p0 + 4][cc];
            }
            #pragma unroll
            for (int mi = 0; mi < 2; mi++)
                #pragma unroll
                for (int ni = 0; ni < 4; ni++) {
                    float* c = acc[mi][ni];
                    mma16816(c, aH[mi][0], aH[mi][1], aH[mi][2], aH[mi][3], bH[ni][0], bH[ni][1]);
                    mma16816(c, aH[mi][0], aH[mi][1], aH[mi][2], aH[mi][3], bL[ni][0], bL[ni][1]);
                    mma16816(c, aL[mi][0], aL[mi][1], aL[mi][2], aL[mi][3], bH[ni][0], bH[ni][1]);
                }
        }
        __syncthreads();
    }

    #pragma unroll
    for (int mi = 0; mi < 2; mi++) {
        int r0 = mbase + wr + mi * 16 + grp;
        #pragma unroll
        for (int ni = 0; ni < 4; ni++) {
            int c0 = nbase + wc + ni * 8 + tig * 2;
            float2 bv = *(const float2*)&bias[c0];
            __stcs((float2*)&C[(size_t)r0 * N + c0],
                   make_float2(acc[mi][ni][0] + bv.x, acc[mi][ni][1] + bv.y));
            __stcs((float2*)&C[(size_t)(r0 + 8) * N + c0],
                   make_float2(acc[mi][ni][2] + bv.x, acc[mi][ni][3] + bv.y));
        }
    }
    __threadfence();
    __syncthreads();
    if (tid == 0) atomicAdd(&g_done[tc], 1);
}

// ---------------- persistent scan kernel ----------------
// 128 CTAs x 512 thr (16 warps). Warp = (kq8 = warp>>1, mtp = warp&1):
// K-eighth kq8, m-tiles {2*mtp, 2*mtp+1}, all 4 gate n-tiles.
// Each B-fragment is read by 2 warps (was 4) -> SMEM LDS traffic halved.
__global__ __launch_bounds__(512, 1) void scan_kernel(
    const float* __restrict__ Wh, const float* __restrict__ c0,
    float* __restrict__ out)
{
    extern __shared__ char smem[];
    uint4*  sWh  = reinterpret_cast<uint4*>(smem);                   // [64][4][32] uint4 = 128KB
    float4* zsf4 = reinterpret_cast<float4*>(smem + 131072);         // [8][512] float4 = 64KB
    float*  hs   = reinterpret_cast<float*>(smem + 131072 + 65536);  // [512]
    float*  cs   = hs + 512;                                          // [512]

    const int j = blockIdx.x, tid = threadIdx.x;
    const int lane = tid & 31, warp = tid >> 5;
    const int grp = lane >> 2, tig = lane & 3;
    const int kq8 = warp >> 1;              // K-eighth 0..7
    const int mtp = warp & 1;               // m-tile pair 0..1
    const int mt0 = mtp * 2, mt1 = mt0 + 1; // this warp's two m-tiles
    const int kb = kq8 * 8;

    // ---- one-time: Wh slice -> SMEM B-fragments ----
    for (int it = 0; it < 16; it++) {
        int slot = tid + it * 512;                   // 8192 slots
        int sl = slot & 31, nt = (slot >> 5) & 3, kk = slot >> 7;
        int sg = sl >> 2, st_ = sl & 3;
        int col = nt * 1024 + j * 8 + sg;
        int k0 = kk * 16 + 2 * st_;
        float w0 = Wh[(size_t)k0 * ZN + col];
        float w1 = Wh[(size_t)(k0 + 1) * ZN + col];
        float w8 = Wh[(size_t)(k0 + 8) * ZN + col];
        float w9 = Wh[(size_t)(k0 + 9) * ZN + col];
        uint4 v;
        pack2(w0, w1, v.x, v.z);
        pack2(w8, w9, v.y, v.w);
        sWh[(kk * 4 + nt) * 32 + sl] = v;
    }
    {
        int row = tid >> 3, col = tid & 7;
        cs[tid] = c0[(size_t)row * HQ + j * 8 + col];
    }
    __syncthreads();

    const size_t OFF_C = (size_t)BQ * TQ * HQ;
    const size_t OFF_H = OFF_C + (size_t)BQ * HQ;

    for (int s = 0; s < TQ; s++) {
        const int buf = s & 1, nbuf = buf ^ 1;
        // gate on phase-1 t-chunk availability
        if ((s & 63) == 0) {
            if (tid == 0) {
                while (ld_acq(&g_done[s >> 6]) < 2048) __nanosleep(128);
            }
            __syncthreads();
        }
        // gate on all CTAs having published h(s)
        if (s > 0) {
            if (tid < NCTA) {
                while (ld_acq(&g_flag[tid]) < s) __nanosleep(32);
            }
            __syncthreads();
        }

        // prefetch xz (DRAM, read-once streaming); consumed after the MMA loop
        float xzv[4];
        {
            int row = tid >> 3, col = tid & 7;
            const float* xp = &g_xz[((size_t)row * TQ + s) * ZN + j * 8 + col];
            xzv[0] = __ldcs(xp);
            xzv[1] = __ldcs(xp + 1024);
            xzv[2] = __ldcs(xp + 2048);
            xzv[3] = __ldcs(xp + 3072);
        }

        float acc0[4][4], acc1[4][4];        // [nt][q] for mt0 / mt1
        #pragma unroll
        for (int nt = 0; nt < 4; nt++)
            #pragma unroll
            for (int q = 0; q < 4; q++) { acc0[nt][q] = 0.f; acc1[nt][q] = 0.f; }

        // distance-1 prefetched A-frag loop over this warp's K-eighth, 2 m-tiles
        uint4 nH0 = ldg_cg_v4(&g_hfH[buf][kb][mt0][lane]);
        uint4 nL0 = ldg_cg_v4(&g_hfL[buf][kb][mt0][lane]);
        uint4 nH1 = ldg_cg_v4(&g_hfH[buf][kb][mt1][lane]);
        uint4 nL1 = ldg_cg_v4(&g_hfL[buf][kb][mt1][lane]);
        #pragma unroll
        for (int i = 0; i < 8; i++) {
            uint4 AH0 = nH0, AL0 = nL0, AH1 = nH1, AL1 = nL1;
            if (i + 1 < 8) {
                nH0 = ldg_cg_v4(&g_hfH[buf][kb + i + 1][mt0][lane]);
                nL0 = ldg_cg_v4(&g_hfL[buf][kb + i + 1][mt0][lane]);
                nH1 = ldg_cg_v4(&g_hfH[buf][kb + i + 1][mt1][lane]);
                nL1 = ldg_cg_v4(&g_hfL[buf][kb + i + 1][mt1][lane]);
            }
            const int kk = kb + i;
            #pragma unroll
            for (int nt = 0; nt < 4; nt++) {
                uint4 Bv = sWh[(kk * 4 + nt) * 32 + lane];   // loaded ONCE, used by both m-tiles
                mma16816(acc0[nt], AH0.x, AH0.y, AH0.z, AH0.w, Bv.x, Bv.y);
                mma16816(acc0[nt], AH0.x, AH0.y, AH0.z, AH0.w, Bv.z, Bv.w);
                mma16816(acc0[nt], AL0.x, AL0.y, AL0.z, AL0.w, Bv.x, Bv.y);
                mma16816(acc1[nt], AH1.x, AH1.y, AH1.z, AH1.w, Bv.x, Bv.y);
                mma16816(acc1[nt], AH1.x, AH1.y, AH1.z, AH1.w, Bv.z, Bv.w);
                mma16816(acc1[nt], AL1.x, AL1.y, AL1.z, AL1.w, Bv.x, Bv.y);
            }
        }

        // stage K-eighth partials: all 4 gates per element as one float4
        {
            #pragma unroll
            for (int q = 0; q < 4; q++) {
                int roff = grp + ((q >> 1) << 3);
                int col  = 2 * tig + (q & 1);
                zsf4[kq8 * 512 + (mt0 * 16 + roff) * 8 + col] =
                    make_float4(acc0[0][q], acc0[1][q], acc0[2][q], acc0[3][q]);
                zsf4[kq8 * 512 + (mt1 * 16 + roff) * 8 + col] =
                    make_float4(acc1[0][q], acc1[1][q], acc1[2][q], acc1[3][q]);
            }
        }
        __syncthreads();

        // gates + state update (reduce the eight K-slices); 1 elem/thread
        {
            int row = tid >> 3, col = tid & 7;
            float4 z = zsf4[tid];
            #pragma unroll
            for (int kz = 1; kz < 8; kz++) {
                float4 p = zsf4[kz * 512 + tid];
                z.x += p.x; z.y += p.y; z.z += p.z; z.w += p.w;
            }
            float zi = z.x + xzv[0];
            float zf = z.y + xzv[1];
            float zg = z.z + xzv[2];
            float zo = z.w + xzv[3];
            float c  = cs[tid];
            float nc = sig_fast(zf) * c + sig_fast(zi) * tanh_acc(zg);
            float nh = sig_fast(zo) * tanh_acc(nc);
            cs[tid] = nc;
            hs[tid] = nh;
            __stcs(&out[((size_t)row * TQ + s) * HQ + j * 8 + col], nh);
            if (s == TQ - 1) {
                __stcs(&out[OFF_C + (size_t)row * HQ + j * 8 + col], nc);
                __stcs(&out[OFF_H + (size_t)row * HQ + j * 8 + col], nh);
            }
        }
        __syncthreads();

        // publish new h as A-fragments into buffer nbuf
        if (tid < 128) {
            int mt2 = tid >> 5, ln = tid & 31;
            int g2 = ln >> 2, t2 = ln & 3;
            int r0 = mt2 * 16 + g2, r1 = r0 + 8, cc = 2 * t2;
            uint2 H, L;
            pack2(hs[r0 * 8 + cc], hs[r0 * 8 + cc + 1], H.x, L.x);
            pack2(hs[r1 * 8 + cc], hs[r1 * 8 + cc + 1], H.y, L.y);
            uint2* dH = reinterpret_cast<uint2*>(&g_hfH[nbuf][j >> 1][mt2][ln]);
            uint2* dL = reinterpret_cast<uint2*>(&g_hfL[nbuf][j >> 1][mt2][ln]);
            dH[j & 1] = H;
            dL[j & 1] = L;
        }
        __threadfence();
        __syncthreads();
        if (tid == 0) atomicExch(&g_flag[j], s + 1);
    }
}

// ---------------- launch: forked capture, phase1 overlaps the scan ----------------
extern "C" void kernel_launch(void* const* d_in, const int* in_sizes, int n_in,
                              void* d_out, int out_size)
{
    (void)in_sizes; (void)n_in; (void)out_size;
    const float* x  = (const float*)d_in[0];
    const float* h0 = (const float*)d_in[1];
    const float* c0 = (const float*)d_in[2];
    const float* Wi = (const float*)d_in[3];
    const float* Wh = (const float*)d_in[4];
    const float* b  = (const float*)d_in[5];
    float* out = (float*)d_out;

    float* xz_p = nullptr;
    cudaGetSymbolAddress((void**)&xz_p, g_xz);

    const int SCAN_SMEM = 131072 + 65536 + 2048 + 2048;   // 200704

    static cudaStream_t s2 = nullptr;
    static cudaEvent_t evA = nullptr, evB = nullptr;
    static bool inited = false;
    if (!inited) {
        cudaStreamCreateWithFlags(&s2, cudaStreamNonBlocking);
        cudaEventCreateWithFlags(&evA, cudaEventDisableTiming);
        cudaEventCreateWithFlags(&evB, cudaEventDisableTiming);
        cudaFuncSetAttribute(scan_kernel, cudaFuncAttributeMaxDynamicSharedMemorySize, SCAN_SMEM);
        inited = true;
    }

    init_kernel<<<32, 256>>>(h0);

    // fork: phase-1 GEMM on s2, ordered after init
    cudaEventRecord(evA, 0);
    cudaStreamWaitEvent(s2, evA, 0);
    gemm_split_kernel<<<16384, 256, 0, s2>>>(x, Wi, b, xz_p, ZN, DQ);
    cudaEventRecord(evB, s2);

    // scan runs concurrently on the main stream; chunk-gated on g_done
    scan_kernel<<<NCTA, 512, SCAN_SMEM>>>(Wh, c0, out);

    // join
    cudaStreamWaitEvent(0, evB, 0);
}

// round 13
// speedup vs baseline: 1.3884x; 1.0734x over previous
#include <cuda_runtime.h>
#include <cuda_bf16.h>
#include <cuda_fp16.h>
#include <cstdint>
#include <cstddef>

#define BQ 64
#define TQ 512
#define DQ 1024
#define HQ 1024
#define ZN 4096   // 4H
#define NCTA 128  // scan CTAs; CTA j owns h cols [8j, 8j+8)

// ---------------- scratch (allocation-free __device__ globals) ----------------
__device__ float g_xz[(size_t)BQ * TQ * ZN];          // 512 MB: x @ Wi + b
// h in MMA A-fragment order, fp16, double-buffered by step parity:
// [buf][k16-chunk 0..63][m-tile 0..3][lane] = uint4 (a0,a1,a2,a3 as half2)
__device__ uint4 g_hf[2][64][4][32];
__device__ int   g_flag[NCTA];
__device__ int   g_done[8];                            // phase-1 t-chunk completion

// ---------------- helpers ----------------
__device__ __forceinline__ void bsplit(float v, uint16_t& h, uint16_t& l) {
    __nv_bfloat16 bh = __float2bfloat16(v);
    __nv_bfloat16 bl = __float2bfloat16(v - __bfloat162float(bh));
    h = __bfloat16_as_ushort(bh);
    l = __bfloat16_as_ushort(bl);
}
__device__ __forceinline__ void pack2(float v0, float v1, uint32_t& hi, uint32_t& lo) {
    uint16_t h0, l0, h1, l1;
    bsplit(v0, h0, l0); bsplit(v1, h1, l1);
    hi = (uint32_t)h0 | ((uint32_t)h1 << 16);
    lo = (uint32_t)l0 | ((uint32_t)l1 << 16);
}
// fp16 pack of two floats
__device__ __forceinline__ uint32_t pack2h(float v0, float v1) {
    __half2 p = __floats2half2_rn(v0, v1);
    return *reinterpret_cast<uint32_t*>(&p);
}
// fp16 2-term split pack: (hi pair, lo pair)
__device__ __forceinline__ void wsplit2(float v0, float v1, uint32_t& hi, uint32_t& lo) {
    __half h0 = __float2half_rn(v0), h1 = __float2half_rn(v1);
    __half l0 = __float2half_rn(v0 - __half2float(h0));
    __half l1 = __float2half_rn(v1 - __half2float(h1));
    __half2 ph = __halves2half2(h0, h1), pl = __halves2half2(l0, l1);
    hi = *reinterpret_cast<uint32_t*>(&ph);
    lo = *reinterpret_cast<uint32_t*>(&pl);
}
// bf16 MMA (phase 1)
__device__ __forceinline__ void mma16816(float c[4], uint32_t a0, uint32_t a1,
                                         uint32_t a2, uint32_t a3,
                                         uint32_t b0, uint32_t b1) {
    asm volatile(
        "mma.sync.aligned.m16n8k16.row.col.f32.bf16.bf16.f32 "
        "{%0,%1,%2,%3},{%4,%5,%6,%7},{%8,%9},{%0,%1,%2,%3};"
        : "+f"(c[0]), "+f"(c[1]), "+f"(c[2]), "+f"(c[3])
        : "r"(a0), "r"(a1), "r"(a2), "r"(a3), "r"(b0), "r"(b1));
}
// fp16 MMA (scan)
__device__ __forceinline__ void mma16816h(float c[4], uint32_t a0, uint32_t a1,
                                          uint32_t a2, uint32_t a3,
                                          uint32_t b0, uint32_t b1) {
    asm volatile(
        "mma.sync.aligned.m16n8k16.row.col.f32.f16.f16.f32 "
        "{%0,%1,%2,%3},{%4,%5,%6,%7},{%8,%9},{%0,%1,%2,%3};"
        : "+f"(c[0]), "+f"(c[1]), "+f"(c[2]), "+f"(c[3])
        : "r"(a0), "r"(a1), "r"(a2), "r"(a3), "r"(b0), "r"(b1));
}
__device__ __forceinline__ uint4 ldg_cg_v4(const uint4* p) {
    uint4 v;
    asm volatile("ld.global.cg.v4.b32 {%0,%1,%2,%3},[%4];"
                 : "=r"(v.x), "=r"(v.y), "=r"(v.z), "=r"(v.w) : "l"(p));
    return v;
}
__device__ __forceinline__ int ld_acq(const int* p) {
    int v;
    asm volatile("ld.global.acquire.gpu.b32 %0,[%1];" : "=r"(v) : "l"(p) : "memory");
    return v;
}
// 1-MUFU approx sigmoid (abs err ~2.4e-4): 0.5 + 0.5*tanh.approx(x/2)
__device__ __forceinline__ float sig_fast(float x) {
    float y;
    asm("tanh.approx.f32 %0,%1;" : "=f"(y) : "f"(0.5f * x));
    return fmaf(0.5f, y, 0.5f);
}
// 2-MUFU accurate tanh (~1e-6): 2/(1+e^{-2x}) - 1
__device__ __forceinline__ float tanh_acc(float x) {
    float e = __expf(-2.0f * x);
    return __fdividef(2.0f, 1.0f + e) - 1.0f;
}

// ---------------- init: h0 -> fp16 frag buffer 0, reset flags/counters ----------------
__global__ __launch_bounds__(256) void init_kernel(const float* __restrict__ h0) {
    int u = blockIdx.x * 256 + threadIdx.x;          // 8192 = 64*4*32
    if (u < NCTA) g_flag[u] = 0;
    if (u < 8)    g_done[u] = 0;
    int lane = u & 31, mt = (u >> 5) & 3, kk = u >> 7;
    int grp = lane >> 2, tig = lane & 3;
    int r0 = mt * 16 + grp, r1 = r0 + 8;
    int k0 = kk * 16 + 2 * tig;
    float2 v00 = *(const float2*)&h0[(size_t)r0 * HQ + k0];
    float2 v10 = *(const float2*)&h0[(size_t)r1 * HQ + k0];
    float2 v01 = *(const float2*)&h0[(size_t)r0 * HQ + k0 + 8];
    float2 v11 = *(const float2*)&h0[(size_t)r1 * HQ + k0 + 8];
    uint4 F;
    F.x = pack2h(v00.x, v00.y);
    F.y = pack2h(v10.x, v10.y);
    F.z = pack2h(v01.x, v01.y);
    F.w = pack2h(v11.x, v11.y);
    g_hf[0][kk][mt][lane] = F;
}

// ---------------- phase 1: xz = x @ Wi + b  (M=32768,N=4096,K=1024) ----------------
// 1-D grid ordered by t-chunk: id = tc*2048 + b*32 + n. CTA tile 64x128, BK=32.
// bf16 3-term split (unchanged — accuracy of xz preserved).
__global__ __launch_bounds__(256, 2) void gemm_split_kernel(
    const float* __restrict__ A, const float* __restrict__ Bm,
    const float* __restrict__ bias, float* __restrict__ C, int N, int K)
{
    __shared__ uint32_t AsH[64][20], AsL[64][20];
    __shared__ uint32_t BsH[16][136], BsL[16][136];

    const int tid  = threadIdx.x;
    const int lane = tid & 31, warp = tid >> 5;
    const int grp = lane >> 2, tig = lane & 3;
    const int wr = (warp >> 2) << 5;
    const int wc = (warp & 3) << 5;

    const int id  = blockIdx.x;
    const int tc  = id >> 11;            // t-chunk 0..7
    const int rem = id & 2047;
    const int bb  = rem >> 5, nn = rem & 31;
    const int mbase = (bb * 8 + tc) * 64;
    const int nbase = nn * 128;

    float acc[2][4][4];
    #pragma unroll
    for (int i = 0; i < 2; i++)
        #pragma unroll
        for (int j = 0; j < 4; j++)
            #pragma unroll
            for (int q = 0; q < 4; q++) acc[i][j][q] = 0.f;

    for (int k0 = 0; k0 < K; k0 += 32) {
        #pragma unroll
        for (int i = 0; i < 2; i++) {
            int idx = tid + i * 256;
            int r = idx >> 3, q = idx & 7;
            float4 v = *reinterpret_cast<const float4*>(&A[(size_t)(mbase + r) * K + k0 + q * 4]);
            pack2(v.x, v.y, AsH[r][q * 2],     AsL[r][q * 2]);
            pack2(v.z, v.w, AsH[r][q * 2 + 1], AsL[r][q * 2 + 1]);
        }
        #pragma unroll
        for (int i = 0; i < 2; i++) {
            int idx = tid + i * 256;
            int p = idx >> 5, ng = idx & 31;
            const float4 r0 = *reinterpret_cast<const float4*>(&Bm[(size_t)(k0 + 2 * p) * N + nbase + ng * 4]);
            const float4 r1 = *reinterpret_cast<const float4*>(&Bm[(size_t)(k0 + 2 * p + 1) * N + nbase + ng * 4]);
            pack2(r0.x, r1.x, BsH[p][ng * 4 + 0], BsL[p][ng * 4 + 0]);
            pack2(r0.y, r1.y, BsH[p][ng * 4 + 1], BsL[p][ng * 4 + 1]);
            pack2(r0.z, r1.z, BsH[p][ng * 4 + 2], BsL[p][ng * 4 + 2]);
            pack2(r0.w, r1.w, BsH[p][ng * 4 + 3], BsL[p][ng * 4 + 3]);
        }
        __syncthreads();

        #pragma unroll
        for (int kk = 0; kk < 2; kk++) {
            uint32_t aH[2][4], aL[2][4], bH[4][2], bL[4][2];
            #pragma unroll
            for (int mi = 0; mi < 2; mi++) {
                int r0 = wr + mi * 16 + grp, r1 = r0 + 8;
                int pq = kk * 8 + tig;
                aH[mi][0] = AsH[r0][pq];     aL[mi][0] = AsL[r0][pq];
                aH[mi][1] = AsH[r1][pq];     aL[mi][1] = AsL[r1][pq];
                aH[mi][2] = AsH[r0][pq + 4]; aL[mi][2] = AsL[r0][pq + 4];
                aH[mi][3] = AsH[r1][pq + 4]; aL[mi][3] = AsL[r1][pq + 4];
            }
            #pragma unroll
            for (int ni = 0; ni < 4; ni++) {
                int cc = wc + ni * 8 + grp;
                int p0 = kk * 8 + tig;
                bH[ni][0] = BsH[p0][cc];     bL[ni][0] = BsL[p0][cc];
                bH[ni][1] = BsH[p0 + 4][cc]; bL[ni][1] = BsL[p0 + 4][cc];
            }
            #pragma unroll
            for (int mi = 0; mi < 2; mi++)
                #pragma unroll
                for (int ni = 0; ni < 4; ni++) {
                    float* c = acc[mi][ni];
                    mma16816(c, aH[mi][0], aH[mi][1], aH[mi][2], aH[mi][3], bH[ni][0], bH[ni][1]);
                    mma16816(c, aH[mi][0], aH[mi][1], aH[mi][2], aH[mi][3], bL[ni][0], bL[ni][1]);
                    mma16816(c, aL[mi][0], aL[mi][1], aL[mi][2], aL[mi][3], bH[ni][0], bH[ni][1]);
                }
        }
        __syncthreads();
    }

    #pragma unroll
    for (int mi = 0; mi < 2; mi++) {
        int r0 = mbase + wr + mi * 16 + grp;
        #pragma unroll
        for (int ni = 0; ni < 4; ni++) {
            int c0 = nbase + wc + ni * 8 + tig * 2;
            float2 bv = *(const float2*)&bias[c0];
            __stcs((float2*)&C[(size_t)r0 * N + c0],
                   make_float2(acc[mi][ni][0] + bv.x, acc[mi][ni][1] + bv.y));
            __stcs((float2*)&C[(size_t)(r0 + 8) * N + c0],
                   make_float2(acc[mi][ni][2] + bv.x, acc[mi][ni][3] + bv.y));
        }
    }
    __threadfence();
    __syncthreads();
    if (tid == 0) atomicAdd(&g_done[tc], 1);
}

// ---------------- persistent scan kernel ----------------
// 128 CTAs x 512 thr (16 warps). Warp = (kq8 = warp>>1, mtp = warp&1):
// K-eighth kq8, m-tiles {2*mtp, 2*mtp+1}, all 4 gate n-tiles.
// fp16 2-term: z = h_f16 @ Wh_hi + h_f16 @ Wh_lo  (2 MMAs per B-frag).
__global__ __launch_bounds__(512, 1) void scan_kernel(
    const float* __restrict__ Wh, const float* __restrict__ c0,
    float* __restrict__ out)
{
    extern __shared__ char smem[];
    uint4*  sWh  = reinterpret_cast<uint4*>(smem);                   // [64][4][32] uint4 = 128KB
    float4* zsf4 = reinterpret_cast<float4*>(smem + 131072);         // [8][512] float4 = 64KB
    float*  hs   = reinterpret_cast<float*>(smem + 131072 + 65536);  // [512]
    float*  cs   = hs + 512;                                          // [512]

    const int j = blockIdx.x, tid = threadIdx.x;
    const int lane = tid & 31, warp = tid >> 5;
    const int grp = lane >> 2, tig = lane & 3;
    const int kq8 = warp >> 1;              // K-eighth 0..7
    const int mtp = warp & 1;               // m-tile pair 0..1
    const int mt0 = mtp * 2, mt1 = mt0 + 1; // this warp's two m-tiles
    const int kb = kq8 * 8;

    // ---- one-time: Wh slice -> SMEM B-fragments (fp16 hi/lo split) ----
    for (int it = 0; it < 16; it++) {
        int slot = tid + it * 512;                   // 8192 slots
        int sl = slot & 31, nt = (slot >> 5) & 3, kk = slot >> 7;
        int sg = sl >> 2, st_ = sl & 3;
        int col = nt * 1024 + j * 8 + sg;
        int k0 = kk * 16 + 2 * st_;
        float w0 = Wh[(size_t)k0 * ZN + col];
        float w1 = Wh[(size_t)(k0 + 1) * ZN + col];
        float w8 = Wh[(size_t)(k0 + 8) * ZN + col];
        float w9 = Wh[(size_t)(k0 + 9) * ZN + col];
        uint4 v;   // (b0_hi, b1_hi, b0_lo, b1_lo)
        wsplit2(w0, w1, v.x, v.z);
        wsplit2(w8, w9, v.y, v.w);
        sWh[(kk * 4 + nt) * 32 + sl] = v;
    }
    {
        int row = tid >> 3, col = tid & 7;
        cs[tid] = c0[(size_t)row * HQ + j * 8 + col];
    }
    __syncthreads();

    const size_t OFF_C = (size_t)BQ * TQ * HQ;
    const size_t OFF_H = OFF_C + (size_t)BQ * HQ;

    for (int s = 0; s < TQ; s++) {
        const int buf = s & 1, nbuf = buf ^ 1;
        // gate on phase-1 t-chunk availability
        if ((s & 63) == 0) {
            if (tid == 0) {
                while (ld_acq(&g_done[s >> 6]) < 2048) __nanosleep(128);
            }
            __syncthreads();
        }
        // gate on all CTAs having published h(s)
        if (s > 0) {
            if (tid < NCTA) {
                while (ld_acq(&g_flag[tid]) < s) __nanosleep(32);
            }
            __syncthreads();
        }

        // prefetch xz (DRAM, read-once streaming); consumed after the MMA loop
        float xzv[4];
        {
            int row = tid >> 3, col = tid & 7;
            const float* xp = &g_xz[((size_t)row * TQ + s) * ZN + j * 8 + col];
            xzv[0] = __ldcs(xp);
            xzv[1] = __ldcs(xp + 1024);
            xzv[2] = __ldcs(xp + 2048);
            xzv[3] = __ldcs(xp + 3072);
        }

        float acc0[4][4], acc1[4][4];        // [nt][q] for mt0 / mt1
        #pragma unroll
        for (int nt = 0; nt < 4; nt++)
            #pragma unroll
            for (int q = 0; q < 4; q++) { acc0[nt][q] = 0.f; acc1[nt][q] = 0.f; }

        // distance-1 prefetched fp16 A-frag loop over this warp's K-eighth, 2 m-tiles
        uint4 nA0 = ldg_cg_v4(&g_hf[buf][kb][mt0][lane]);
        uint4 nA1 = ldg_cg_v4(&g_hf[buf][kb][mt1][lane]);
        #pragma unroll
        for (int i = 0; i < 8; i++) {
            uint4 A0 = nA0, A1 = nA1;
            if (i + 1 < 8) {
                nA0 = ldg_cg_v4(&g_hf[buf][kb + i + 1][mt0][lane]);
                nA1 = ldg_cg_v4(&g_hf[buf][kb + i + 1][mt1][lane]);
            }
            const int kk = kb + i;
            #pragma unroll
            for (int nt = 0; nt < 4; nt++) {
                uint4 Bv = sWh[(kk * 4 + nt) * 32 + lane];   // loaded ONCE, used by both m-tiles
                mma16816h(acc0[nt], A0.x, A0.y, A0.z, A0.w, Bv.x, Bv.y);
                mma16816h(acc0[nt], A0.x, A0.y, A0.z, A0.w, Bv.z, Bv.w);
                mma16816h(acc1[nt], A1.x, A1.y, A1.z, A1.w, Bv.x, Bv.y);
                mma16816h(acc1[nt], A1.x, A1.y, A1.z, A1.w, Bv.z, Bv.w);
            }
        }

        // stage K-eighth partials: all 4 gates per element as one float4
        {
            #pragma unroll
            for (int q = 0; q < 4; q++) {
                int roff = grp + ((q >> 1) << 3);
                int col  = 2 * tig + (q & 1);
                zsf4[kq8 * 512 + (mt0 * 16 + roff) * 8 + col] =
                    make_float4(acc0[0][q], acc0[1][q], acc0[2][q], acc0[3][q]);
                zsf4[kq8 * 512 + (mt1 * 16 + roff) * 8 + col] =
                    make_float4(acc1[0][q], acc1[1][q], acc1[2][q], acc1[3][q]);
            }
        }
        __syncthreads();

        // gates + state update (reduce the eight K-slices); 1 elem/thread
        {
            int row = tid >> 3, col = tid & 7;
            float4 z = zsf4[tid];
            #pragma unroll
            for (int kz = 1; kz < 8; kz++) {
                float4 p = zsf4[kz * 512 + tid];
                z.x += p.x; z.y += p.y; z.z += p.z; z.w += p.w;
            }
            float zi = z.x + xzv[0];
            float zf = z.y + xzv[1];
            float zg = z.z + xzv[2];
            float zo = z.w + xzv[3];
            float c  = cs[tid];
            float nc = sig_fast(zf) * c + sig_fast(zi) * tanh_acc(zg);
            float nh = sig_fast(zo) * tanh_acc(nc);
            cs[tid] = nc;
            hs[tid] = nh;
            __stcs(&out[((size_t)row * TQ + s) * HQ + j * 8 + col], nh);
            if (s == TQ - 1) {
                __stcs(&out[OFF_C + (size_t)row * HQ + j * 8 + col], nc);
                __stcs(&out[OFF_H + (size_t)row * HQ + j * 8 + col], nh);
            }
        }
        __syncthreads();

        // publish new h as fp16 A-fragments into buffer nbuf
        if (tid < 128) {
            int mt2 = tid >> 5, ln = tid & 31;
            int g2 = ln >> 2, t2 = ln & 3;
            int r0 = mt2 * 16 + g2, r1 = r0 + 8, cc = 2 * t2;
            uint2 F;
            F.x = pack2h(hs[r0 * 8 + cc], hs[r0 * 8 + cc + 1]);
            F.y = pack2h(hs[r1 * 8 + cc], hs[r1 * 8 + cc + 1]);
            uint2* dF = reinterpret_cast<uint2*>(&g_hf[nbuf][j >> 1][mt2][ln]);
            dF[j & 1] = F;
        }
        __threadfence();
        __syncthreads();
        if (tid == 0) atomicExch(&g_flag[j], s + 1);
    }
}

// ---------------- launch: forked capture, phase1 overlaps the scan ----------------
extern "C" void kernel_launch(void* const* d_in, const int* in_sizes, int n_in,
                              void* d_out, int out_size)
{
    (void)in_sizes; (void)n_in; (void)out_size;
    const float* x  = (const float*)d_in[0];
    const float* h0 = (const float*)d_in[1];
    const float* c0 = (const float*)d_in[2];
    const float* Wi = (const float*)d_in[3];
    const float* Wh = (const float*)d_in[4];
    const float* b  = (const float*)d_in[5];
    float* out = (float*)d_out;

    float* xz_p = nullptr;
    cudaGetSymbolAddress((void**)&xz_p, g_xz);

    const int SCAN_SMEM = 131072 + 65536 + 2048 + 2048;   // 200704

    static cudaStream_t s2 = nullptr;
    static cudaEvent_t evA = nullptr, evB = nullptr;
    static bool inited = false;
    if (!inited) {
        cudaStreamCreateWithFlags(&s2, cudaStreamNonBlocking);
        cudaEventCreateWithFlags(&evA, cudaEventDisableTiming);
        cudaEventCreateWithFlags(&evB, cudaEventDisableTiming);
        cudaFuncSetAttribute(scan_kernel, cudaFuncAttributeMaxDynamicSharedMemorySize, SCAN_SMEM);
        inited = true;
    }

    init_kernel<<<32, 256>>>(h0);

    // fork: phase-1 GEMM on s2, ordered after init
    cudaEventRecord(evA, 0);
    cudaStreamWaitEvent(s2, evA, 0);
    gemm_split_kernel<<<16384, 256, 0, s2>>>(x, Wi, b, xz_p, ZN, DQ);
    cudaEventRecord(evB, s2);

    // scan runs concurrently on the main stream; chunk-gated on g_done
    scan_kernel<<<NCTA, 512, SCAN_SMEM>>>(Wh, c0, out);

    // join
    cudaStreamWaitEvent(0, evB, 0);
}

// round 14
// speedup vs baseline: 1.5402x; 1.1094x over previous
#include <cuda_runtime.h>
#include <cuda_bf16.h>
#include <cuda_fp16.h>
#include <cstdint>
#include <cstddef>

#define BQ 64
#define TQ 512
#define DQ 1024
#define HQ 1024
#define ZN 4096   // 4H
#define NCTA 128  // scan CTAs; CTA j owns h cols [8j, 8j+8)

// ---------------- scratch (allocation-free __device__ globals) ----------------
__device__ float g_xz[(size_t)BQ * TQ * ZN];          // 512 MB: x @ Wi + b
// h in MMA A-fragment order, fp16, double-buffered by step parity:
// [buf][k16-chunk 0..63][m-tile 0..3][lane] = uint4 (a0,a1,a2,a3 as half2)
__device__ uint4 g_hf[2][64][4][32];
__device__ int   g_flag[NCTA];
__device__ int   g_done[8];                            // phase-1 t-chunk completion

// ---------------- helpers ----------------
__device__ __forceinline__ void bsplit(float v, uint16_t& h, uint16_t& l) {
    __nv_bfloat16 bh = __float2bfloat16(v);
    __nv_bfloat16 bl = __float2bfloat16(v - __bfloat162float(bh));
    h = __bfloat16_as_ushort(bh);
    l = __bfloat16_as_ushort(bl);
}
__device__ __forceinline__ void pack2(float v0, float v1, uint32_t& hi, uint32_t& lo) {
    uint16_t h0, l0, h1, l1;
    bsplit(v0, h0, l0); bsplit(v1, h1, l1);
    hi = (uint32_t)h0 | ((uint32_t)h1 << 16);
    lo = (uint32_t)l0 | ((uint32_t)l1 << 16);
}
// fp16 pack of two floats
__device__ __forceinline__ uint32_t pack2h(float v0, float v1) {
    __half2 p = __floats2half2_rn(v0, v1);
    return *reinterpret_cast<uint32_t*>(&p);
}
// bf16 MMA (phase 1)
__device__ __forceinline__ void mma16816(float c[4], uint32_t a0, uint32_t a1,
                                         uint32_t a2, uint32_t a3,
                                         uint32_t b0, uint32_t b1) {
    asm volatile(
        "mma.sync.aligned.m16n8k16.row.col.f32.bf16.bf16.f32 "
        "{%0,%1,%2,%3},{%4,%5,%6,%7},{%8,%9},{%0,%1,%2,%3};"
        : "+f"(c[0]), "+f"(c[1]), "+f"(c[2]), "+f"(c[3])
        : "r"(a0), "r"(a1), "r"(a2), "r"(a3), "r"(b0), "r"(b1));
}
// fp16 MMA (scan)
__device__ __forceinline__ void mma16816h(float c[4], uint32_t a0, uint32_t a1,
                                          uint32_t a2, uint32_t a3,
                                          uint32_t b0, uint32_t b1) {
    asm volatile(
        "mma.sync.aligned.m16n8k16.row.col.f32.f16.f16.f32 "
        "{%0,%1,%2,%3},{%4,%5,%6,%7},{%8,%9},{%0,%1,%2,%3};"
        : "+f"(c[0]), "+f"(c[1]), "+f"(c[2]), "+f"(c[3])
        : "r"(a0), "r"(a1), "r"(a2), "r"(a3), "r"(b0), "r"(b1));
}
__device__ __forceinline__ uint4 ldg_cg_v4(const uint4* p) {
    uint4 v;
    asm volatile("ld.global.cg.v4.b32 {%0,%1,%2,%3},[%4];"
                 : "=r"(v.x), "=r"(v.y), "=r"(v.z), "=r"(v.w) : "l"(p));
    return v;
}
__device__ __forceinline__ int ld_acq(const int* p) {
    int v;
    asm volatile("ld.global.acquire.gpu.b32 %0,[%1];" : "=r"(v) : "l"(p) : "memory");
    return v;
}
// 1-MUFU approx sigmoid (abs err ~2.4e-4): 0.5 + 0.5*tanh.approx(x/2)
__device__ __forceinline__ float sig_fast(float x) {
    float y;
    asm("tanh.approx.f32 %0,%1;" : "=f"(y) : "f"(0.5f * x));
    return fmaf(0.5f, y, 0.5f);
}
// 2-MUFU accurate tanh (~1e-6): 2/(1+e^{-2x}) - 1
__device__ __forceinline__ float tanh_acc(float x) {
    float e = __expf(-2.0f * x);
    return __fdividef(2.0f, 1.0f + e) - 1.0f;
}

// ---------------- init: h0 -> fp16 frag buffer 0, reset flags/counters ----------------
__global__ __launch_bounds__(256) void init_kernel(const float* __restrict__ h0) {
    int u = blockIdx.x * 256 + threadIdx.x;          // 8192 = 64*4*32
    if (u < NCTA) g_flag[u] = 0;
    if (u < 8)    g_done[u] = 0;
    int lane = u & 31, mt = (u >> 5) & 3, kk = u >> 7;
    int grp = lane >> 2, tig = lane & 3;
    int r0 = mt * 16 + grp, r1 = r0 + 8;
    int k0 = kk * 16 + 2 * tig;
    float2 v00 = *(const float2*)&h0[(size_t)r0 * HQ + k0];
    float2 v10 = *(const float2*)&h0[(size_t)r1 * HQ + k0];
    float2 v01 = *(const float2*)&h0[(size_t)r0 * HQ + k0 + 8];
    float2 v11 = *(const float2*)&h0[(size_t)r1 * HQ + k0 + 8];
    uint4 F;
    F.x = pack2h(v00.x, v00.y);
    F.y = pack2h(v10.x, v10.y);
    F.z = pack2h(v01.x, v01.y);
    F.w = pack2h(v11.x, v11.y);
    g_hf[0][kk][mt][lane] = F;
}

// ---------------- phase 1: xz = x @ Wi + b  (M=32768,N=4096,K=1024) ----------------
// 1-D grid ordered by t-chunk: id = tc*2048 + b*32 + n. CTA tile 64x128, BK=32.
// bf16 3-term split (unchanged — accuracy of xz preserved).
__global__ __launch_bounds__(256, 2) void gemm_split_kernel(
    const float* __restrict__ A, const float* __restrict__ Bm,
    const float* __restrict__ bias, float* __restrict__ C, int N, int K)
{
    __shared__ uint32_t AsH[64][20], AsL[64][20];
    __shared__ uint32_t BsH[16][136], BsL[16][136];

    const int tid  = threadIdx.x;
    const int lane = tid & 31, warp = tid >> 5;
    const int grp = lane >> 2, tig = lane & 3;
    const int wr = (warp >> 2) << 5;
    const int wc = (warp & 3) << 5;

    const int id  = blockIdx.x;
    const int tc  = id >> 11;            // t-chunk 0..7
    const int rem = id & 2047;
    const int bb  = rem >> 5, nn = rem & 31;
    const int mbase = (bb * 8 + tc) * 64;
    const int nbase = nn * 128;

    float acc[2][4][4];
    #pragma unroll
    for (int i = 0; i < 2; i++)
        #pragma unroll
        for (int j = 0; j < 4; j++)
            #pragma unroll
            for (int q = 0; q < 4; q++) acc[i][j][q] = 0.f;

    for (int k0 = 0; k0 < K; k0 += 32) {
        #pragma unroll
        for (int i = 0; i < 2; i++) {
            int idx = tid + i * 256;
            int r = idx >> 3, q = idx & 7;
            float4 v = *reinterpret_cast<const float4*>(&A[(size_t)(mbase + r) * K + k0 + q * 4]);
            pack2(v.x, v.y, AsH[r][q * 2],     AsL[r][q * 2]);
            pack2(v.z, v.w, AsH[r][q * 2 + 1], AsL[r][q * 2 + 1]);
        }
        #pragma unroll
        for (int i = 0; i < 2; i++) {
            int idx = tid + i * 256;
            int p = idx >> 5, ng = idx & 31;
            const float4 r0 = *reinterpret_cast<const float4*>(&Bm[(size_t)(k0 + 2 * p) * N + nbase + ng * 4]);
            const float4 r1 = *reinterpret_cast<const float4*>(&Bm[(size_t)(k0 + 2 * p + 1) * N + nbase + ng * 4]);
            pack2(r0.x, r1.x, BsH[p][ng * 4 + 0], BsL[p][ng * 4 + 0]);
            pack2(r0.y, r1.y, BsH[p][ng * 4 + 1], BsL[p][ng * 4 + 1]);
            pack2(r0.z, r1.z, BsH[p][ng * 4 + 2], BsL[p][ng * 4 + 2]);
            pack2(r0.w, r1.w, BsH[p][ng * 4 + 3], BsL[p][ng * 4 + 3]);
        }
        __syncthreads();

        #pragma unroll
        for (int kk = 0; kk < 2; kk++) {
            uint32_t aH[2][4], aL[2][4], bH[4][2], bL[4][2];
            #pragma unroll
            for (int mi = 0; mi < 2; mi++) {
                int r0 = wr + mi * 16 + grp, r1 = r0 + 8;
                int pq = kk * 8 + tig;
                aH[mi][0] = AsH[r0][pq];     aL[mi][0] = AsL[r0][pq];
                aH[mi][1] = AsH[r1][pq];     aL[mi][1] = AsL[r1][pq];
                aH[mi][2] = AsH[r0][pq + 4]; aL[mi][2] = AsL[r0][pq + 4];
                aH[mi][3] = AsH[r1][pq + 4]; aL[mi][3] = AsL[r1][pq + 4];
            }
            #pragma unroll
            for (int ni = 0; ni < 4; ni++) {
                int cc = wc + ni * 8 + grp;
                int p0 = kk * 8 + tig;
                bH[ni][0] = BsH[p0][cc];     bL[ni][0] = BsL[p0][cc];
                bH[ni][1] = BsH[p0 + 4][cc]; bL[ni][1] = BsL[p0 + 4][cc];
            }
            #pragma unroll
            for (int mi = 0; mi < 2; mi++)
                #pragma unroll
                for (int ni = 0; ni < 4; ni++) {
                    float* c = acc[mi][ni];
                    mma16816(c, aH[mi][0], aH[mi][1], aH[mi][2], aH[mi][3], bH[ni][0], bH[ni][1]);
                    mma16816(c, aH[mi][0], aH[mi][1], aH[mi][2], aH[mi][3], bL[ni][0], bL[ni][1]);
                    mma16816(c, aL[mi][0], aL[mi][1], aL[mi][2], aL[mi][3], bH[ni][0], bH[ni][1]);
                }
        }
        __syncthreads();
    }

    #pragma unroll
    for (int mi = 0; mi < 2; mi++) {
        int r0 = mbase + wr + mi * 16 + grp;
        #pragma unroll
        for (int ni = 0; ni < 4; ni++) {
            int c0 = nbase + wc + ni * 8 + tig * 2;
            float2 bv = *(const float2*)&bias[c0];
            __stcs((float2*)&C[(size_t)r0 * N + c0],
                   make_float2(acc[mi][ni][0] + bv.x, acc[mi][ni][1] + bv.y));
            __stcs((float2*)&C[(size_t)(r0 + 8) * N + c0],
                   make_float2(acc[mi][ni][2] + bv.x, acc[mi][ni][3] + bv.y));
        }
    }
    __threadfence();
    __syncthreads();
    if (tid == 0) atomicAdd(&g_done[tc], 1);
}

// ---------------- persistent scan kernel ----------------
// 128 CTAs x 512 thr (16 warps). Warp = (kq8 = warp>>1, mtp = warp&1):
// K-eighth kq8, m-tiles {2*mtp, 2*mtp+1}, all 4 gate n-tiles.
// fp16 single-term: z = h_f16 @ Wh_f16 (1 MMA per B-frag per m-tile).
__global__ __launch_bounds__(512, 1) void scan_kernel(
    const float* __restrict__ Wh, const float* __restrict__ c0,
    float* __restrict__ out)
{
    extern __shared__ char smem[];
    uint2*  sWh  = reinterpret_cast<uint2*>(smem);                   // [64][4][32] uint2 = 64KB
    float4* zsf4 = reinterpret_cast<float4*>(smem + 65536);          // [8][512] float4 = 64KB
    float*  hs   = reinterpret_cast<float*>(smem + 65536 + 65536);   // [512]
    float*  cs   = hs + 512;                                          // [512]

    const int j = blockIdx.x, tid = threadIdx.x;
    const int lane = tid & 31, warp = tid >> 5;
    const int grp = lane >> 2, tig = lane & 3;
    const int kq8 = warp >> 1;              // K-eighth 0..7
    const int mtp = warp & 1;               // m-tile pair 0..1
    const int mt0 = mtp * 2, mt1 = mt0 + 1; // this warp's two m-tiles
    const int kb = kq8 * 8;

    // ---- one-time: Wh slice -> SMEM B-fragments (fp16) ----
    for (int it = 0; it < 16; it++) {
        int slot = tid + it * 512;                   // 8192 slots
        int sl = slot & 31, nt = (slot >> 5) & 3, kk = slot >> 7;
        int sg = sl >> 2, st_ = sl & 3;
        int col = nt * 1024 + j * 8 + sg;
        int k0 = kk * 16 + 2 * st_;
        float w0 = Wh[(size_t)k0 * ZN + col];
        float w1 = Wh[(size_t)(k0 + 1) * ZN + col];
        float w8 = Wh[(size_t)(k0 + 8) * ZN + col];
        float w9 = Wh[(size_t)(k0 + 9) * ZN + col];
        uint2 v;   // (b0, b1)
        v.x = pack2h(w0, w1);
        v.y = pack2h(w8, w9);
        sWh[(kk * 4 + nt) * 32 + sl] = v;
    }
    {
        int row = tid >> 3, col = tid & 7;
        cs[tid] = c0[(size_t)row * HQ + j * 8 + col];
    }
    __syncthreads();

    const size_t OFF_C = (size_t)BQ * TQ * HQ;
    const size_t OFF_H = OFF_C + (size_t)BQ * HQ;

    for (int s = 0; s < TQ; s++) {
        const int buf = s & 1, nbuf = buf ^ 1;
        // gate on phase-1 t-chunk availability
        if ((s & 63) == 0) {
            if (tid == 0) {
                while (ld_acq(&g_done[s >> 6]) < 2048) __nanosleep(128);
            }
            __syncthreads();
        }
        // gate on all CTAs having published h(s)
        if (s > 0) {
            if (tid < NCTA) {
                while (ld_acq(&g_flag[tid]) < s) __nanosleep(32);
            }
            __syncthreads();
        }

        // prefetch xz (DRAM, read-once streaming); consumed after the MMA loop
        float xzv[4];
        {
            int row = tid >> 3, col = tid & 7;
            const float* xp = &g_xz[((size_t)row * TQ + s) * ZN + j * 8 + col];
            xzv[0] = __ldcs(xp);
            xzv[1] = __ldcs(xp + 1024);
            xzv[2] = __ldcs(xp + 2048);
            xzv[3] = __ldcs(xp + 3072);
        }

        float acc0[4][4], acc1[4][4];        // [nt][q] for mt0 / mt1
        #pragma unroll
        for (int nt = 0; nt < 4; nt++)
            #pragma unroll
            for (int q = 0; q < 4; q++) { acc0[nt][q] = 0.f; acc1[nt][q] = 0.f; }

        // distance-1 prefetched fp16 A-frag loop over this warp's K-eighth, 2 m-tiles
        uint4 nA0 = ldg_cg_v4(&g_hf[buf][kb][mt0][lane]);
        uint4 nA1 = ldg_cg_v4(&g_hf[buf][kb][mt1][lane]);
        #pragma unroll
        for (int i = 0; i < 8; i++) {
            uint4 A0 = nA0, A1 = nA1;
            if (i + 1 < 8) {
                nA0 = ldg_cg_v4(&g_hf[buf][kb + i + 1][mt0][lane]);
                nA1 = ldg_cg_v4(&g_hf[buf][kb + i + 1][mt1][lane]);
            }
            const int kk = kb + i;
            #pragma unroll
            for (int nt = 0; nt < 4; nt++) {
                uint2 Bv = sWh[(kk * 4 + nt) * 32 + lane];   // loaded ONCE, used by both m-tiles
                mma16816h(acc0[nt], A0.x, A0.y, A0.z, A0.w, Bv.x, Bv.y);
                mma16816h(acc1[nt], A1.x, A1.y, A1.z, A1.w, Bv.x, Bv.y);
            }
        }

        // stage K-eighth partials: all 4 gates per element as one float4
        {
            #pragma unroll
            for (int q = 0; q < 4; q++) {
                int roff = grp + ((q >> 1) << 3);
                int col  = 2 * tig + (q & 1);
                zsf4[kq8 * 512 + (mt0 * 16 + roff) * 8 + col] =
                    make_float4(acc0[0][q], acc0[1][q], acc0[2][q], acc0[3][q]);
                zsf4[kq8 * 512 + (mt1 * 16 + roff) * 8 + col] =
                    make_float4(acc1[0][q], acc1[1][q], acc1[2][q], acc1[3][q]);
            }
        }
        __syncthreads();

        // gates + state update (reduce the eight K-slices); 1 elem/thread
        {
            int row = tid >> 3, col = tid & 7;
            float4 z = zsf4[tid];
            #pragma unroll
            for (int kz = 1; kz < 8; kz++) {
                float4 p = zsf4[kz * 512 + tid];
                z.x += p.x; z.y += p.y; z.z += p.z; z.w += p.w;
            }
            float zi = z.x + xzv[0];
            float zf = z.y + xzv[1];
            float zg = z.z + xzv[2];
            float zo = z.w + xzv[3];
            float c  = cs[tid];
            float nc = sig_fast(zf) * c + sig_fast(zi) * tanh_acc(zg);
            float nh = sig_fast(zo) * tanh_acc(nc);
            cs[tid] = nc;
            hs[tid] = nh;
            __stcs(&out[((size_t)row * TQ + s) * HQ + j * 8 + col], nh);
            if (s == TQ - 1) {
                __stcs(&out[OFF_C + (size_t)row * HQ + j * 8 + col], nc);
                __stcs(&out[OFF_H + (size_t)row * HQ + j * 8 + col], nh);
            }
        }
        __syncthreads();

        // publish new h as fp16 A-fragments into buffer nbuf
        if (tid < 128) {
            int mt2 = tid >> 5, ln = tid & 31;
            int g2 = ln >> 2, t2 = ln & 3;
            int r0 = mt2 * 16 + g2, r1 = r0 + 8, cc = 2 * t2;
            uint2 F;
            F.x = pack2h(hs[r0 * 8 + cc], hs[r0 * 8 + cc + 1]);
            F.y = pack2h(hs[r1 * 8 + cc], hs[r1 * 8 + cc + 1]);
            uint2* dF = reinterpret_cast<uint2*>(&g_hf[nbuf][j >> 1][mt2][ln]);
            dF[j & 1] = F;
        }
        __threadfence();
        __syncthreads();
        if (tid == 0) atomicExch(&g_flag[j], s + 1);
    }
}

// ---------------- launch: forked capture, phase1 overlaps the scan ----------------
extern "C" void kernel_launch(void* const* d_in, const int* in_sizes, int n_in,
                              void* d_out, int out_size)
{
    (void)in_sizes; (void)n_in; (void)out_size;
    const float* x  = (const float*)d_in[0];
    const float* h0 = (const float*)d_in[1];
    const float* c0 = (const float*)d_in[2];
    const float* Wi = (const float*)d_in[3];
    const float* Wh = (const float*)d_in[4];
    const float* b  = (const float*)d_in[5];
    float* out = (float*)d_out;

    float* xz_p = nullptr;
    cudaGetSymbolAddress((void**)&xz_p, g_xz);

    const int SCAN_SMEM = 65536 + 65536 + 2048 + 2048;   // 135168

    static cudaStream_t s2 = nullptr;
    static cudaEvent_t evA = nullptr, evB = nullptr;
    static bool inited = false;
    if (!inited) {
        cudaStreamCreateWithFlags(&s2, cudaStreamNonBlocking);
        cudaEventCreateWithFlags(&evA, cudaEventDisableTiming);
        cudaEventCreateWithFlags(&evB, cudaEventDisableTiming);
        cudaFuncSetAttribute(scan_kernel, cudaFuncAttributeMaxDynamicSharedMemorySize, SCAN_SMEM);
        inited = true;
    }

    init_kernel<<<32, 256>>>(h0);

    // fork: phase-1 GEMM on s2, ordered after init
    cudaEventRecord(evA, 0);
    cudaStreamWaitEvent(s2, evA, 0);
    gemm_split_kernel<<<16384, 256, 0, s2>>>(x, Wi, b, xz_p, ZN, DQ);
    cudaEventRecord(evB, s2);

    // scan runs concurrently on the main stream; chunk-gated on g_done
    scan_kernel<<<NCTA, 512, SCAN_SMEM>>>(Wh, c0, out);

    // join
    cudaStreamWaitEvent(0, evB, 0);
}

// round 15
// speedup vs baseline: 1.5854x; 1.0293x over previous
#include <cuda_runtime.h>
#include <cuda_bf16.h>
#include <cuda_fp16.h>
#include <cstdint>
#include <cstddef>

#define BQ 64
#define TQ 512
#define DQ 1024
#define HQ 1024
#define ZN 4096   // 4H
#define NCTA 128  // scan CTAs; CTA j owns h cols [8j, 8j+8)
#define CLSZ 4    // scan cluster size; rank r TMA-multicasts h slice r

// ---------------- scratch (allocation-free __device__ globals) ----------------
__device__ float g_xz[(size_t)BQ * TQ * ZN];          // 512 MB: x @ Wi + b
// h in MMA A-fragment order, fp16, double-buffered by step parity:
// [buf][k16-chunk 0..63][m-tile 0..3][lane] = uint4 (a0,a1,a2,a3 as half2)
__device__ uint4 g_hf[2][64][4][32];
__device__ int   g_flag[NCTA];
__device__ int   g_done[8];                            // phase-1 t-chunk completion

// ---------------- helpers ----------------
__device__ __forceinline__ void bsplit(float v, uint16_t& h, uint16_t& l) {
    __nv_bfloat16 bh = __float2bfloat16(v);
    __nv_bfloat16 bl = __float2bfloat16(v - __bfloat162float(bh));
    h = __bfloat16_as_ushort(bh);
    l = __bfloat16_as_ushort(bl);
}
__device__ __forceinline__ void pack2(float v0, float v1, uint32_t& hi, uint32_t& lo) {
    uint16_t h0, l0, h1, l1;
    bsplit(v0, h0, l0); bsplit(v1, h1, l1);
    hi = (uint32_t)h0 | ((uint32_t)h1 << 16);
    lo = (uint32_t)l0 | ((uint32_t)l1 << 16);
}
// fp16 pack of two floats
__device__ __forceinline__ uint32_t pack2h(float v0, float v1) {
    __half2 p = __floats2half2_rn(v0, v1);
    return *reinterpret_cast<uint32_t*>(&p);
}
// bf16 MMA (phase 1)
__device__ __forceinline__ void mma16816(float c[4], uint32_t a0, uint32_t a1,
                                         uint32_t a2, uint32_t a3,
                                         uint32_t b0, uint32_t b1) {
    asm volatile(
        "mma.sync.aligned.m16n8k16.row.col.f32.bf16.bf16.f32 "
        "{%0,%1,%2,%3},{%4,%5,%6,%7},{%8,%9},{%0,%1,%2,%3};"
        : "+f"(c[0]), "+f"(c[1]), "+f"(c[2]), "+f"(c[3])
        : "r"(a0), "r"(a1), "r"(a2), "r"(a3), "r"(b0), "r"(b1));
}
// fp16 MMA (scan)
__device__ __forceinline__ void mma16816h(float c[4], uint32_t a0, uint32_t a1,
                                          uint32_t a2, uint32_t a3,
                                          uint32_t b0, uint32_t b1) {
    asm volatile(
        "mma.sync.aligned.m16n8k16.row.col.f32.f16.f16.f32 "
        "{%0,%1,%2,%3},{%4,%5,%6,%7},{%8,%9},{%0,%1,%2,%3};"
        : "+f"(c[0]), "+f"(c[1]), "+f"(c[2]), "+f"(c[3])
        : "r"(a0), "r"(a1), "r"(a2), "r"(a3), "r"(b0), "r"(b1));
}
__device__ __forceinline__ int ld_acq(const int* p) {
    int v;
    asm volatile("ld.global.acquire.gpu.b32 %0,[%1];" : "=r"(v) : "l"(p) : "memory");
    return v;
}
// 1-MUFU approx sigmoid (abs err ~2.4e-4): 0.5 + 0.5*tanh.approx(x/2)
__device__ __forceinline__ float sig_fast(float x) {
    float y;
    asm("tanh.approx.f32 %0,%1;" : "=f"(y) : "f"(0.5f * x));
    return fmaf(0.5f, y, 0.5f);
}
// 2-MUFU accurate tanh (~1e-6): 2/(1+e^{-2x}) - 1
__device__ __forceinline__ float tanh_acc(float x) {
    float e = __expf(-2.0f * x);
    return __fdividef(2.0f, 1.0f + e) - 1.0f;
}
// ---- mbarrier / TMA / cluster primitives ----
__device__ __forceinline__ void mbar_init(uint32_t a, uint32_t cnt) {
    asm volatile("mbarrier.init.shared.b64 [%0], %1;" :: "r"(a), "r"(cnt) : "memory");
}
__device__ __forceinline__ void mbar_expect(uint32_t a, uint32_t tx) {
    asm volatile("mbarrier.arrive.expect_tx.shared.b64 _, [%0], %1;"
                 :: "r"(a), "r"(tx) : "memory");
}
__device__ __forceinline__ void mbar_wait(uint32_t a, uint32_t ph) {
    uint32_t done;
    asm volatile(
        "{\n\t.reg .pred p;\n\t"
        "mbarrier.try_wait.parity.acquire.cta.shared::cta.b64 p, [%1], %2;\n\t"
        "selp.b32 %0, 1, 0, p;\n\t}"
        : "=r"(done) : "r"(a), "r"(ph) : "memory");
    if (!done) {
        asm volatile(
            "{\n\t.reg .pred P1;\n"
            "WAIT_LOOP_%=:\n\t"
            "mbarrier.try_wait.parity.acquire.cta.shared::cta.b64 P1, [%0], %1, 0x989680;\n\t"
            "@P1 bra.uni WAIT_DONE_%=;\n\t"
            "bra.uni WAIT_LOOP_%=;\n"
            "WAIT_DONE_%=:\n\t}"
            :: "r"(a), "r"(ph) : "memory");
    }
}
__device__ __forceinline__ void tma_bulk_mc(uint32_t dst, const void* src,
                                            uint32_t bytes, uint32_t mbar, uint16_t mask) {
    asm volatile(
        "cp.async.bulk.shared::cluster.global.mbarrier::complete_tx::bytes"
        ".multicast::cluster [%0], [%1], %2, [%3], %4;"
        :: "r"(dst), "l"(src), "r"(bytes), "r"(mbar), "h"(mask) : "memory");
}
__device__ __forceinline__ void cluster_arrive() {
    asm volatile("barrier.cluster.arrive.aligned;" ::: "memory");
}
__device__ __forceinline__ void cluster_wait() {
    asm volatile("barrier.cluster.wait.aligned;" ::: "memory");
}
__device__ __forceinline__ uint32_t cl_rank() {
    uint32_t r;
    asm("mov.u32 %0, %%cluster_ctarank;" : "=r"(r));
    return r;
}

// ---------------- init: h0 -> fp16 frag buffer 0, reset flags/counters ----------------
__global__ __launch_bounds__(256) void init_kernel(const float* __restrict__ h0) {
    int u = blockIdx.x * 256 + threadIdx.x;          // 8192 = 64*4*32
    if (u < NCTA) g_flag[u] = 0;
    if (u < 8)    g_done[u] = 0;
    int lane = u & 31, mt = (u >> 5) & 3, kk = u >> 7;
    int grp = lane >> 2, tig = lane & 3;
    int r0 = mt * 16 + grp, r1 = r0 + 8;
    int k0 = kk * 16 + 2 * tig;
    float2 v00 = *(const float2*)&h0[(size_t)r0 * HQ + k0];
    float2 v10 = *(const float2*)&h0[(size_t)r1 * HQ + k0];
    float2 v01 = *(const float2*)&h0[(size_t)r0 * HQ + k0 + 8];
    float2 v11 = *(const float2*)&h0[(size_t)r1 * HQ + k0 + 8];
    uint4 F;
    F.x = pack2h(v00.x, v00.y);
    F.y = pack2h(v10.x, v10.y);
    F.z = pack2h(v01.x, v01.y);
    F.w = pack2h(v11.x, v11.y);
    g_hf[0][kk][mt][lane] = F;
}

// ---------------- phase 1: xz = x @ Wi + b  (M=32768,N=4096,K=1024) ----------------
// 1-D grid ordered by t-chunk: id = tc*2048 + b*32 + n. CTA tile 64x128, BK=32.
// bf16 3-term split (unchanged — accuracy of xz preserved).
__global__ __launch_bounds__(256, 2) void gemm_split_kernel(
    const float* __restrict__ A, const float* __restrict__ Bm,
    const float* __restrict__ bias, float* __restrict__ C, int N, int K)
{
    __shared__ uint32_t AsH[64][20], AsL[64][20];
    __shared__ uint32_t BsH[16][136], BsL[16][136];

    const int tid  = threadIdx.x;
    const int lane = tid & 31, warp = tid >> 5;
    const int grp = lane >> 2, tig = lane & 3;
    const int wr = (warp >> 2) << 5;
    const int wc = (warp & 3) << 5;

    const int id  = blockIdx.x;
    const int tc  = id >> 11;            // t-chunk 0..7
    const int rem = id & 2047;
    const int bb  = rem >> 5, nn = rem & 31;
    const int mbase = (bb * 8 + tc) * 64;
    const int nbase = nn * 128;

    float acc[2][4][4];
    #pragma unroll
    for (int i = 0; i < 2; i++)
        #pragma unroll
        for (int j = 0; j < 4; j++)
            #pragma unroll
            for (int q = 0; q < 4; q++) acc[i][j][q] = 0.f;

    for (int k0 = 0; k0 < K; k0 += 32) {
        #pragma unroll
        for (int i = 0; i < 2; i++) {
            int idx = tid + i * 256;
            int r = idx >> 3, q = idx & 7;
            float4 v = *reinterpret_cast<const float4*>(&A[(size_t)(mbase + r) * K + k0 + q * 4]);
            pack2(v.x, v.y, AsH[r][q * 2],     AsL[r][q * 2]);
            pack2(v.z, v.w, AsH[r][q * 2 + 1], AsL[r][q * 2 + 1]);
        }
        #pragma unroll
        for (int i = 0; i < 2; i++) {
            int idx = tid + i * 256;
            int p = idx >> 5, ng = idx & 31;
            const float4 r0 = *reinterpret_cast<const float4*>(&Bm[(size_t)(k0 + 2 * p) * N + nbase + ng * 4]);
            const float4 r1 = *reinterpret_cast<const float4*>(&Bm[(size_t)(k0 + 2 * p + 1) * N + nbase + ng * 4]);
            pack2(r0.x, r1.x, BsH[p][ng * 4 + 0], BsL[p][ng * 4 + 0]);
            pack2(r0.y, r1.y, BsH[p][ng * 4 + 1], BsL[p][ng * 4 + 1]);
            pack2(r0.z, r1.z, BsH[p][ng * 4 + 2], BsL[p][ng * 4 + 2]);
            pack2(r0.w, r1.w, BsH[p][ng * 4 + 3], BsL[p][ng * 4 + 3]);
        }
        __syncthreads();

        #pragma unroll
        for (int kk = 0; kk < 2; kk++) {
            uint32_t aH[2][4], aL[2][4], bH[4][2], bL[4][2];
            #pragma unroll
            for (int mi = 0; mi < 2; mi++) {
                int r0 = wr + mi * 16 + grp, r1 = r0 + 8;
                int pq = kk * 8 + tig;
                aH[mi][0] = AsH[r0][pq];     aL[mi][0] = AsL[r0][pq];
                aH[mi][1] = AsH[r1][pq];     aL[mi][1] = AsL[r1][pq];
                aH[mi][2] = AsH[r0][pq + 4]; aL[mi][2] = AsL[r0][pq + 4];
                aH[mi][3] = AsH[r1][pq + 4]; aL[mi][3] = AsL[r1][pq + 4];
            }
            #pragma unroll
            for (int ni = 0; ni < 4; ni++) {
                int cc = wc + ni * 8 + grp;
                int p0 = kk * 8 + tig;
                bH[ni][0] = BsH[p0][cc];     bL[ni][0] = BsL[p0][cc];
                bH[ni][1] = BsH[p0 + 4][cc]; bL[ni][1] = BsL[p0 + 4][cc];
            }
            #pragma unroll
            for (int mi = 0; mi < 2; mi++)
                #pragma unroll
                for (int ni = 0; ni < 4; ni++) {
                    float* c = acc[mi][ni];
                    mma16816(c, aH[mi][0], aH[mi][1], aH[mi][2], aH[mi][3], bH[ni][0], bH[ni][1]);
                    mma16816(c, aH[mi][0], aH[mi][1], aH[mi][2], aH[mi][3], bL[ni][0], bL[ni][1]);
                    mma16816(c, aL[mi][0], aL[mi][1], aL[mi][2], aL[mi][3], bH[ni][0], bH[ni][1]);
                }
        }
        __syncthreads();
    }

    #pragma unroll
    for (int mi = 0; mi < 2; mi++) {
        int r0 = mbase + wr + mi * 16 + grp;
        #pragma unroll
        for (int ni = 0; ni < 4; ni++) {
            int c0 = nbase + wc + ni * 8 + tig * 2;
            float2 bv = *(const float2*)&bias[c0];
            __stcs((float2*)&C[(size_t)r0 * N + c0],
                   make_float2(acc[mi][ni][0] + bv.x, acc[mi][ni][1] + bv.y));
            __stcs((float2*)&C[(size_t)(r0 + 8) * N + c0],
                   make_float2(acc[mi][ni][2] + bv.x, acc[mi][ni][3] + bv.y));
        }
    }
    __threadfence();
    __syncthreads();
    if (tid == 0) atomicAdd(&g_done[tc], 1);
}

// ---------------- persistent scan kernel (clusters of 4 + TMA multicast) ----------------
// 128 CTAs x 512 thr (16 warps), 32 clusters of 4. Warp = (kq8 = warp>>1, mtp = warp&1).
// Each step: rank r TMA-multicasts global h slice r (32KB, chunks [16r,16r+16))
// into all 4 cluster CTAs' SMEM; warp kq8 waits mbarrier[kq8>>1] only.
// SMEM: sWh 64K | hbuf 128K | zsf16 32K | mb 64B | hs 2K  = 226 KB
__global__ __launch_bounds__(512, 1) void scan_kernel(
    const float* __restrict__ Wh, const float* __restrict__ c0,
    float* __restrict__ out)
{
    extern __shared__ char smem[];
    uint2* sWh   = reinterpret_cast<uint2*>(smem);                    // [64][4][32] uint2
    uint4* hbuf  = reinterpret_cast<uint4*>(smem + 65536);            // [64][4][32] uint4
    uint2* zsf16 = reinterpret_cast<uint2*>(smem + 196608);           // [8][512] uint2
    float* hs    = reinterpret_cast<float*>(smem + 229440);           // [512]
    const uint32_t smem_u32 = [] (const void* p) {
        uint32_t a;
        asm("{ .reg .u64 t; cvta.to.shared.u64 t, %1; cvt.u32.u64 %0, t; }"
            : "=r"(a) : "l"(p));
        return a;
    }(smem);
    const uint32_t mb    = smem_u32 + 229376;   // 4 mbarriers (8B each)
    const uint32_t hbase = smem_u32 + 65536;    // hbuf shared addr

    const int j = blockIdx.x, tid = threadIdx.x;
    const int lane = tid & 31, warp = tid >> 5;
    const int grp = lane >> 2, tig = lane & 3;
    const int kq8 = warp >> 1;              // K-eighth 0..7
    const int mtp = warp & 1;               // m-tile pair 0..1
    const int mt0 = mtp * 2, mt1 = mt0 + 1;
    const int kb = kq8 * 8;
    const int slice = kq8 >> 1;             // mbarrier index for this warp
    const uint32_t rank = cl_rank();        // 0..3; TMA slice this CTA fetches
    const uint16_t MASK = (1u << CLSZ) - 1u;

    // ---- one-time: Wh slice -> SMEM B-fragments (fp16) ----
    for (int it = 0; it < 16; it++) {
        int slot = tid + it * 512;                   // 8192 slots
        int sl = slot & 31, nt = (slot >> 5) & 3, kk = slot >> 7;
        int sg = sl >> 2, st_ = sl & 3;
        int col = nt * 1024 + j * 8 + sg;
        int k0 = kk * 16 + 2 * st_;
        float w0 = Wh[(size_t)k0 * ZN + col];
        float w1 = Wh[(size_t)(k0 + 1) * ZN + col];
        float w8 = Wh[(size_t)(k0 + 8) * ZN + col];
        float w9 = Wh[(size_t)(k0 + 9) * ZN + col];
        uint2 v;
        v.x = pack2h(w0, w1);
        v.y = pack2h(w8, w9);
        sWh[(kk * 4 + nt) * 32 + sl] = v;
    }
    // c state lives in a register (1 elem/thread)
    float creg;
    {
        int row = tid >> 3, col = tid & 7;
        creg = c0[(size_t)row * HQ + j * 8 + col];
    }
    // mbarriers + expect for step 0
    if (tid == 0) {
        #pragma unroll
        for (int r = 0; r < CLSZ; r++) mbar_init(mb + r * 8, 1);
        #pragma unroll
        for (int r = 0; r < CLSZ; r++) mbar_expect(mb + r * 8, 32768);
    }
    __syncthreads();
    cluster_arrive();
    cluster_wait();
    // initial TMA: fetch h(0) slice (init_kernel already wrote g_hf[0])
    if (tid == 0) {
        const char* src = (const char*)&g_hf[0][0][0][0] + rank * 32768;
        tma_bulk_mc(hbase + rank * 32768, src, 32768, mb + rank * 8, MASK);
    }

    const size_t OFF_C = (size_t)BQ * TQ * HQ;
    const size_t OFF_H = OFF_C + (size_t)BQ * HQ;

    for (int s = 0; s < TQ; s++) {
        // gate on phase-1 t-chunk availability
        if ((s & 63) == 0) {
            if (tid == 0) {
                while (ld_acq(&g_done[s >> 6]) < 2048) __nanosleep(128);
            }
            __syncthreads();
        }

        // prefetch xz (independent of h)
        float xzv[4];
        {
            int row = tid >> 3, col = tid & 7;
            const float* xp = &g_xz[((size_t)row * TQ + s) * ZN + j * 8 + col];
            xzv[0] = __ldcs(xp);
            xzv[1] = __ldcs(xp + 1024);
            xzv[2] = __ldcs(xp + 2048);
            xzv[3] = __ldcs(xp + 3072);
        }

        // wait for THIS warp's h slice to land in SMEM
        mbar_wait(mb + slice * 8, (uint32_t)(s & 1));

        float acc0[4][4], acc1[4][4];
        #pragma unroll
        for (int nt = 0; nt < 4; nt++)
            #pragma unroll
            for (int q = 0; q < 4; q++) { acc0[nt][q] = 0.f; acc1[nt][q] = 0.f; }

        #pragma unroll
        for (int i = 0; i < 8; i++) {
            const int kk = kb + i;
            uint4 A0 = hbuf[(kk * 4 + mt0) * 32 + lane];
            uint4 A1 = hbuf[(kk * 4 + mt1) * 32 + lane];
            #pragma unroll
            for (int nt = 0; nt < 4; nt++) {
                uint2 Bv = sWh[(kk * 4 + nt) * 32 + lane];
                mma16816h(acc0[nt], A0.x, A0.y, A0.z, A0.w, Bv.x, Bv.y);
                mma16816h(acc1[nt], A1.x, A1.y, A1.z, A1.w, Bv.x, Bv.y);
            }
        }
        cluster_arrive();   // this CTA is done reading hbuf for step s

        // stage K-eighth partials (fp16 pairs: (zi,zf),(zg,zo))
        {
            #pragma unroll
            for (int q = 0; q < 4; q++) {
                int roff = grp + ((q >> 1) << 3);
                int col  = 2 * tig + (q & 1);
                zsf16[kq8 * 512 + (mt0 * 16 + roff) * 8 + col] =
                    make_uint2(pack2h(acc0[0][q], acc0[1][q]), pack2h(acc0[2][q], acc0[3][q]));
                zsf16[kq8 * 512 + (mt1 * 16 + roff) * 8 + col] =
                    make_uint2(pack2h(acc1[0][q], acc1[1][q]), pack2h(acc1[2][q], acc1[3][q]));
            }
        }
        __syncthreads();

        // post expect_tx for next step (all warps passed their phase-s waits)
        if (tid == 0 && s + 1 < TQ) {
            #pragma unroll
            for (int r = 0; r < CLSZ; r++) mbar_expect(mb + r * 8, 32768);
        }

        // gates + state update (reduce 8 fp16 K-slices); 1 elem/thread
        {
            int row = tid >> 3, col = tid & 7;
            float zi = xzv[0], zf = xzv[1], zg = xzv[2], zo = xzv[3];
            #pragma unroll
            for (int kz = 0; kz < 8; kz++) {
                uint2 v = zsf16[kz * 512 + tid];
                __half2 a = *reinterpret_cast<__half2*>(&v.x);
                __half2 b = *reinterpret_cast<__half2*>(&v.y);
                float2 fa = __half22float2(a), fb = __half22float2(b);
                zi += fa.x; zf += fa.y; zg += fb.x; zo += fb.y;
            }
            float nc = sig_fast(zf) * creg + sig_fast(zi) * tanh_acc(zg);
            float nh = sig_fast(zo) * tanh_acc(nc);
            creg = nc;
            hs[tid] = nh;
            __stcs(&out[((size_t)row * TQ + s) * HQ + j * 8 + col], nh);
            if (s == TQ - 1) {
                __stcs(&out[OFF_C + (size_t)row * HQ + j * 8 + col], nc);
                __stcs(&out[OFF_H + (size_t)row * HQ + j * 8 + col], nh);
            }
        }
        __syncthreads();

        // publish new h as fp16 A-fragments into global buffer (s+1)&1
        if (tid < 128) {
            int mt2 = tid >> 5, ln = tid & 31;
            int g2 = ln >> 2, t2 = ln & 3;
            int r0 = mt2 * 16 + g2, r1 = r0 + 8, cc = 2 * t2;
            uint2 F;
            F.x = pack2h(hs[r0 * 8 + cc], hs[r0 * 8 + cc + 1]);
            F.y = pack2h(hs[r1 * 8 + cc], hs[r1 * 8 + cc + 1]);
            uint2* dF = reinterpret_cast<uint2*>(&g_hf[(s + 1) & 1][j >> 1][mt2][ln]);
            dF[j & 1] = F;
        }
        __threadfence();
        __syncthreads();
        if (tid == 0) atomicExch(&g_flag[j], s + 1);

        // SMEM hbuf safe to overwrite once all 4 cluster CTAs arrived (post-MMA)
        cluster_wait();

        // fetch h(s+1): rank's slice, gated on its 32 producers
        if (s + 1 < TQ && warp == 0) {
            const int f = 32 * (int)rank + lane;
            while (ld_acq(&g_flag[f]) < s + 1) __nanosleep(16);
            __syncwarp();
            if (lane == 0) {
                const char* src = (const char*)&g_hf[(s + 1) & 1][0][0][0] + rank * 32768;
                tma_bulk_mc(hbase + rank * 32768, src, 32768, mb + rank * 8, MASK);
            }
        }
    }
}

// ---------------- launch: forked capture, phase1 overlaps the scan ----------------
extern "C" void kernel_launch(void* const* d_in, const int* in_sizes, int n_in,
                              void* d_out, int out_size)
{
    (void)in_sizes; (void)n_in; (void)out_size;
    const float* x  = (const float*)d_in[0];
    const float* h0 = (const float*)d_in[1];
    const float* c0 = (const float*)d_in[2];
    const float* Wi = (const float*)d_in[3];
    const float* Wh = (const float*)d_in[4];
    const float* b  = (const float*)d_in[5];
    float* out = (float*)d_out;

    float* xz_p = nullptr;
    cudaGetSymbolAddress((void**)&xz_p, g_xz);

    const int SCAN_SMEM = 229440 + 2048;   // 231488 (<= 232448 max)

    static cudaStream_t s2 = nullptr;
    static cudaEvent_t evA = nullptr, evB = nullptr;
    static bool inited = false;
    if (!inited) {
        cudaStreamCreateWithFlags(&s2, cudaStreamNonBlocking);
        cudaEventCreateWithFlags(&evA, cudaEventDisableTiming);
        cudaEventCreateWithFlags(&evB, cudaEventDisableTiming);
        cudaFuncSetAttribute(scan_kernel, cudaFuncAttributeMaxDynamicSharedMemorySize, SCAN_SMEM);
        inited = true;
    }

    init_kernel<<<32, 256>>>(h0);

    // fork: phase-1 GEMM on s2, ordered after init
    cudaEventRecord(evA, 0);
    cudaStreamWaitEvent(s2, evA, 0);
    gemm_split_kernel<<<16384, 256, 0, s2>>>(x, Wi, b, xz_p, ZN, DQ);
    cudaEventRecord(evB, s2);

    // scan: cluster launch (32 clusters of 4) on the default stream
    {
        cudaLaunchConfig_t cfg = {};
        cfg.gridDim = dim3(NCTA, 1, 1);
        cfg.blockDim = dim3(512, 1, 1);
        cfg.dynamicSmemBytes = SCAN_SMEM;
        cfg.stream = 0;
        cudaLaunchAttribute attrs[1];
        attrs[0].id = cudaLaunchAttributeClusterDimension;
        attrs[0].val.clusterDim = {CLSZ, 1, 1};
        cfg.attrs = attrs;
        cfg.numAttrs = 1;
        cudaLaunchKernelEx(&cfg, scan_kernel, Wh, c0, out);
    }

    // join
    cudaStreamWaitEvent(0, evB, 0);
}

// round 16
// speedup vs baseline: 1.5967x; 1.0072x over previous
#include <cuda_runtime.h>
#include <cuda_bf16.h>
#include <cuda_fp16.h>
#include <cstdint>
#include <cstddef>

#define BQ 64
#define TQ 512
#define DQ 1024
#define HQ 1024
#define ZN 4096   // 4H
#define NCTA 128  // scan CTAs; CTA j owns h cols [8j, 8j+8)
#define CLSZ 4    // scan cluster size

// ---------------- scratch (allocation-free __device__ globals) ----------------
__device__ float g_xz[(size_t)BQ * TQ * ZN];          // 512 MB: x @ Wi + b
// h in MMA A-fragment order, fp16, double-buffered by step parity:
// [buf][k16-chunk 0..63][m-tile 0..3][lane] = uint4 (a0,a1,a2,a3 as half2)
__device__ uint4 g_hf[2][64][4][32];
__device__ int   g_flag[NCTA];
__device__ int   g_done[8];                            // phase-1 t-chunk completion

// ---------------- helpers ----------------
__device__ __forceinline__ void bsplit(float v, uint16_t& h, uint16_t& l) {
    __nv_bfloat16 bh = __float2bfloat16(v);
    __nv_bfloat16 bl = __float2bfloat16(v - __bfloat162float(bh));
    h = __bfloat16_as_ushort(bh);
    l = __bfloat16_as_ushort(bl);
}
__device__ __forceinline__ void pack2(float v0, float v1, uint32_t& hi, uint32_t& lo) {
    uint16_t h0, l0, h1, l1;
    bsplit(v0, h0, l0); bsplit(v1, h1, l1);
    hi = (uint32_t)h0 | ((uint32_t)h1 << 16);
    lo = (uint32_t)l0 | ((uint32_t)l1 << 16);
}
// fp16 pack of two floats
__device__ __forceinline__ uint32_t pack2h(float v0, float v1) {
    __half2 p = __floats2half2_rn(v0, v1);
    return *reinterpret_cast<uint32_t*>(&p);
}
// bf16 MMA (phase 1)
__device__ __forceinline__ void mma16816(float c[4], uint32_t a0, uint32_t a1,
                                         uint32_t a2, uint32_t a3,
                                         uint32_t b0, uint32_t b1) {
    asm volatile(
        "mma.sync.aligned.m16n8k16.row.col.f32.bf16.bf16.f32 "
        "{%0,%1,%2,%3},{%4,%5,%6,%7},{%8,%9},{%0,%1,%2,%3};"
        : "+f"(c[0]), "+f"(c[1]), "+f"(c[2]), "+f"(c[3])
        : "r"(a0), "r"(a1), "r"(a2), "r"(a3), "r"(b0), "r"(b1));
}
// fp16 MMA (scan)
__device__ __forceinline__ void mma16816h(float c[4], uint32_t a0, uint32_t a1,
                                          uint32_t a2, uint32_t a3,
                                          uint32_t b0, uint32_t b1) {
    asm volatile(
        "mma.sync.aligned.m16n8k16.row.col.f32.f16.f16.f32 "
        "{%0,%1,%2,%3},{%4,%5,%6,%7},{%8,%9},{%0,%1,%2,%3};"
        : "+f"(c[0]), "+f"(c[1]), "+f"(c[2]), "+f"(c[3])
        : "r"(a0), "r"(a1), "r"(a2), "r"(a3), "r"(b0), "r"(b1));
}
__device__ __forceinline__ int ld_acq(const int* p) {
    int v;
    asm volatile("ld.global.acquire.gpu.b32 %0,[%1];" : "=r"(v) : "l"(p) : "memory");
    return v;
}
// 1-MUFU approx sigmoid (abs err ~2.4e-4): 0.5 + 0.5*tanh.approx(x/2)
__device__ __forceinline__ float sig_fast(float x) {
    float y;
    asm("tanh.approx.f32 %0,%1;" : "=f"(y) : "f"(0.5f * x));
    return fmaf(0.5f, y, 0.5f);
}
// 2-MUFU accurate tanh (~1e-6): 2/(1+e^{-2x}) - 1
__device__ __forceinline__ float tanh_acc(float x) {
    float e = __expf(-2.0f * x);
    return __fdividef(2.0f, 1.0f + e) - 1.0f;
}
// ---- mbarrier / TMA / cluster primitives ----
__device__ __forceinline__ void mbar_init(uint32_t a, uint32_t cnt) {
    asm volatile("mbarrier.init.shared.b64 [%0], %1;" :: "r"(a), "r"(cnt) : "memory");
}
__device__ __forceinline__ void mbar_expect(uint32_t a, uint32_t tx) {
    asm volatile("mbarrier.arrive.expect_tx.shared.b64 _, [%0], %1;"
                 :: "r"(a), "r"(tx) : "memory");
}
__device__ __forceinline__ void mbar_wait(uint32_t a, uint32_t ph) {
    uint32_t done;
    asm volatile(
        "{\n\t.reg .pred p;\n\t"
        "mbarrier.try_wait.parity.acquire.cta.shared::cta.b64 p, [%1], %2;\n\t"
        "selp.b32 %0, 1, 0, p;\n\t}"
        : "=r"(done) : "r"(a), "r"(ph) : "memory");
    if (!done) {
        asm volatile(
            "{\n\t.reg .pred P1;\n"
            "WAIT_LOOP_%=:\n\t"
            "mbarrier.try_wait.parity.acquire.cta.shared::cta.b64 P1, [%0], %1, 0x989680;\n\t"
            "@P1 bra.uni WAIT_DONE_%=;\n\t"
            "bra.uni WAIT_LOOP_%=;\n"
            "WAIT_DONE_%=:\n\t}"
            :: "r"(a), "r"(ph) : "memory");
    }
}
__device__ __forceinline__ void tma_bulk_mc(uint32_t dst, const void* src,
                                            uint32_t bytes, uint32_t mbar, uint16_t mask) {
    asm volatile(
        "cp.async.bulk.shared::cluster.global.mbarrier::complete_tx::bytes"
        ".multicast::cluster [%0], [%1], %2, [%3], %4;"
        :: "r"(dst), "l"(src), "r"(bytes), "r"(mbar), "h"(mask) : "memory");
}
__device__ __forceinline__ void cluster_arrive() {
    asm volatile("barrier.cluster.arrive.aligned;" ::: "memory");
}
__device__ __forceinline__ void cluster_wait() {
    asm volatile("barrier.cluster.wait.aligned;" ::: "memory");
}
__device__ __forceinline__ uint32_t cl_rank() {
    uint32_t r;
    asm("mov.u32 %0, %%cluster_ctarank;" : "=r"(r));
    return r;
}

// ---------------- init: h0 -> fp16 frag buffer 0, reset flags/counters ----------------
__global__ __launch_bounds__(256) void init_kernel(const float* __restrict__ h0) {
    int u = blockIdx.x * 256 + threadIdx.x;          // 8192 = 64*4*32
    if (u < NCTA) g_flag[u] = 0;
    if (u < 8)    g_done[u] = 0;
    int lane = u & 31, mt = (u >> 5) & 3, kk = u >> 7;
    int grp = lane >> 2, tig = lane & 3;
    int r0 = mt * 16 + grp, r1 = r0 + 8;
    int k0 = kk * 16 + 2 * tig;
    float2 v00 = *(const float2*)&h0[(size_t)r0 * HQ + k0];
    float2 v10 = *(const float2*)&h0[(size_t)r1 * HQ + k0];
    float2 v01 = *(const float2*)&h0[(size_t)r0 * HQ + k0 + 8];
    float2 v11 = *(const float2*)&h0[(size_t)r1 * HQ + k0 + 8];
    uint4 F;
    F.x = pack2h(v00.x, v00.y);
    F.y = pack2h(v10.x, v10.y);
    F.z = pack2h(v01.x, v01.y);
    F.w = pack2h(v11.x, v11.y);
    g_hf[0][kk][mt][lane] = F;
}

// ---------------- phase 1: xz = x @ Wi + b  (M=32768,N=4096,K=1024) ----------------
// 1-D grid ordered by t-chunk: id = tc*2048 + b*32 + n. CTA tile 64x128, BK=32.
// bf16 3-term split (unchanged — accuracy of xz preserved).
__global__ __launch_bounds__(256, 2) void gemm_split_kernel(
    const float* __restrict__ A, const float* __restrict__ Bm,
    const float* __restrict__ bias, float* __restrict__ C, int N, int K)
{
    __shared__ uint32_t AsH[64][20], AsL[64][20];
    __shared__ uint32_t BsH[16][136], BsL[16][136];

    const int tid  = threadIdx.x;
    const int lane = tid & 31, warp = tid >> 5;
    const int grp = lane >> 2, tig = lane & 3;
    const int wr = (warp >> 2) << 5;
    const int wc = (warp & 3) << 5;

    const int id  = blockIdx.x;
    const int tc  = id >> 11;            // t-chunk 0..7
    const int rem = id & 2047;
    const int bb  = rem >> 5, nn = rem & 31;
    const int mbase = (bb * 8 + tc) * 64;
    const int nbase = nn * 128;

    float acc[2][4][4];
    #pragma unroll
    for (int i = 0; i < 2; i++)
        #pragma unroll
        for (int j = 0; j < 4; j++)
            #pragma unroll
            for (int q = 0; q < 4; q++) acc[i][j][q] = 0.f;

    for (int k0 = 0; k0 < K; k0 += 32) {
        #pragma unroll
        for (int i = 0; i < 2; i++) {
            int idx = tid + i * 256;
            int r = idx >> 3, q = idx & 7;
            float4 v = *reinterpret_cast<const float4*>(&A[(size_t)(mbase + r) * K + k0 + q * 4]);
            pack2(v.x, v.y, AsH[r][q * 2],     AsL[r][q * 2]);
            pack2(v.z, v.w, AsH[r][q * 2 + 1], AsL[r][q * 2 + 1]);
        }
        #pragma unroll
        for (int i = 0; i < 2; i++) {
            int idx = tid + i * 256;
            int p = idx >> 5, ng = idx & 31;
            const float4 r0 = *reinterpret_cast<const float4*>(&Bm[(size_t)(k0 + 2 * p) * N + nbase + ng * 4]);
            const float4 r1 = *reinterpret_cast<const float4*>(&Bm[(size_t)(k0 + 2 * p + 1) * N + nbase + ng * 4]);
            pack2(r0.x, r1.x, BsH[p][ng * 4 + 0], BsL[p][ng * 4 + 0]);
            pack2(r0.y, r1.y, BsH[p][ng * 4 + 1], BsL[p][ng * 4 + 1]);
            pack2(r0.z, r1.z, BsH[p][ng * 4 + 2], BsL[p][ng * 4 + 2]);
            pack2(r0.w, r1.w, BsH[p][ng * 4 + 3], BsL[p][ng * 4 + 3]);
        }
        __syncthreads();

        #pragma unroll
        for (int kk = 0; kk < 2; kk++) {
            uint32_t aH[2][4], aL[2][4], bH[4][2], bL[4][2];
            #pragma unroll
            for (int mi = 0; mi < 2; mi++) {
                int r0 = wr + mi * 16 + grp, r1 = r0 + 8;
                int pq = kk * 8 + tig;
                aH[mi][0] = AsH[r0][pq];     aL[mi][0] = AsL[r0][pq];
                aH[mi][1] = AsH[r1][pq];     aL[mi][1] = AsL[r1][pq];
                aH[mi][2] = AsH[r0][pq + 4]; aL[mi][2] = AsL[r0][pq + 4];
                aH[mi][3] = AsH[r1][pq + 4]; aL[mi][3] = AsL[r1][pq + 4];
            }
            #pragma unroll
            for (int ni = 0; ni < 4; ni++) {
                int cc = wc + ni * 8 + grp;
                int p0 = kk * 8 + tig;
                bH[ni][0] = BsH[p0][cc];     bL[ni][0] = BsL[p0][cc];
                bH[ni][1] = BsH[p0 + 4][cc]; bL[ni][1] = BsL[p0 + 4][cc];
            }
            #pragma unroll
            for (int mi = 0; mi < 2; mi++)
                #pragma unroll
                for (int ni = 0; ni < 4; ni++) {
                    float* c = acc[mi][ni];
                    mma16816(c, aH[mi][0], aH[mi][1], aH[mi][2], aH[mi][3], bH[ni][0], bH[ni][1]);
                    mma16816(c, aH[mi][0], aH[mi][1], aH[mi][2], aH[mi][3], bL[ni][0], bL[ni][1]);
                    mma16816(c, aL[mi][0], aL[mi][1], aL[mi][2], aL[mi][3], bH[ni][0], bH[ni][1]);
                }
        }
        __syncthreads();
    }

    #pragma unroll
    for (int mi = 0; mi < 2; mi++) {
        int r0 = mbase + wr + mi * 16 + grp;
        #pragma unroll
        for (int ni = 0; ni < 4; ni++) {
            int c0 = nbase + wc + ni * 8 + tig * 2;
            float2 bv = *(const float2*)&bias[c0];
            __stcs((float2*)&C[(size_t)r0 * N + c0],
                   make_float2(acc[mi][ni][0] + bv.x, acc[mi][ni][1] + bv.y));
            __stcs((float2*)&C[(size_t)(r0 + 8) * N + c0],
                   make_float2(acc[mi][ni][2] + bv.x, acc[mi][ni][3] + bv.y));
        }
    }
    __threadfence();
    __syncthreads();
    if (tid == 0) atomicAdd(&g_done[tc], 1);
}

// ---------------- persistent scan kernel (clusters of 4 + sub-sliced TMA multicast) ----------------
// 128 CTAs x 512 thr (16 warps), 32 clusters of 4. Warp = (kq8 = warp>>1, mtp = warp&1).
// 8 sub-slices of 16KB (k-chunks [8u,8u+8)); rank r issues subs 2r (warp0) and 2r+1 (warp1),
// each gated on its 16 producers. Warp kq8 waits mbarrier[kq8] exactly.
// Gates publish h per-thread (st.global.b16) BEFORE the out stores -> shorter handoff.
__global__ __launch_bounds__(512, 1) void scan_kernel(
    const float* __restrict__ Wh, const float* __restrict__ c0,
    float* __restrict__ out)
{
    extern __shared__ char smem[];
    uint2* sWh   = reinterpret_cast<uint2*>(smem);                    // [64][4][32] uint2 = 64KB
    uint4* hbuf  = reinterpret_cast<uint4*>(smem + 65536);            // [64][4][32] uint4 = 128KB
    uint2* zsf16 = reinterpret_cast<uint2*>(smem + 196608);           // [8][512] uint2 = 32KB
    const uint32_t smem_u32 = [] (const void* p) {
        uint32_t a;
        asm("{ .reg .u64 t; cvta.to.shared.u64 t, %1; cvt.u32.u64 %0, t; }"
            : "=r"(a) : "l"(p));
        return a;
    }(smem);
    const uint32_t mb    = smem_u32 + 229376;   // 8 mbarriers (8B each)
    const uint32_t hbase = smem_u32 + 65536;    // hbuf shared addr

    const int j = blockIdx.x, tid = threadIdx.x;
    const int lane = tid & 31, warp = tid >> 5;
    const int grp = lane >> 2, tig = lane & 3;
    const int kq8 = warp >> 1;              // K-eighth 0..7
    const int mtp = warp & 1;               // m-tile pair 0..1
    const int mt0 = mtp * 2, mt1 = mt0 + 1;
    const int kb = kq8 * 8;
    const uint32_t rank = cl_rank();        // 0..3
    const uint16_t MASK = (1u << CLSZ) - 1u;

    // ---- one-time: Wh slice -> SMEM B-fragments (fp16) ----
    for (int it = 0; it < 16; it++) {
        int slot = tid + it * 512;                   // 8192 slots
        int sl = slot & 31, nt = (slot >> 5) & 3, kk = slot >> 7;
        int sg = sl >> 2, st_ = sl & 3;
        int col = nt * 1024 + j * 8 + sg;
        int k0 = kk * 16 + 2 * st_;
        float w0 = Wh[(size_t)k0 * ZN + col];
        float w1 = Wh[(size_t)(k0 + 1) * ZN + col];
        float w8 = Wh[(size_t)(k0 + 8) * ZN + col];
        float w9 = Wh[(size_t)(k0 + 9) * ZN + col];
        uint2 v;
        v.x = pack2h(w0, w1);
        v.y = pack2h(w8, w9);
        sWh[(kk * 4 + nt) * 32 + sl] = v;
    }
    // c state lives in a register (1 elem/thread)
    float creg;
    {
        int row = tid >> 3, col = tid & 7;
        creg = c0[(size_t)row * HQ + j * 8 + col];
    }
    // mbarriers + expects for phase 0
    if (tid == 0) {
        #pragma unroll
        for (int r = 0; r < 8; r++) mbar_init(mb + r * 8, 1);
        #pragma unroll
        for (int r = 0; r < 8; r++) mbar_expect(mb + r * 8, 16384);
    }
    __syncthreads();
    cluster_arrive();
    cluster_wait();
    // initial TMA: warps 0,1 fetch this rank's two sub-slices of h(0)
    if (warp < 2 && lane == 0) {
        const int sub = 2 * (int)rank + warp;
        const char* src = (const char*)&g_hf[0][0][0][0] + sub * 16384;
        tma_bulk_mc(hbase + sub * 16384, src, 16384, mb + sub * 8, MASK);
    }

    const size_t OFF_C = (size_t)BQ * TQ * HQ;
    const size_t OFF_H = OFF_C + (size_t)BQ * HQ;

    for (int s = 0; s < TQ; s++) {
        // gate on phase-1 t-chunk availability
        if ((s & 63) == 0) {
            if (tid == 0) {
                while (ld_acq(&g_done[s >> 6]) < 2048) __nanosleep(128);
            }
            __syncthreads();
        }

        // prefetch xz (independent of h)
        float xzv[4];
        {
            int row = tid >> 3, col = tid & 7;
            const float* xp = &g_xz[((size_t)row * TQ + s) * ZN + j * 8 + col];
            xzv[0] = __ldcs(xp);
            xzv[1] = __ldcs(xp + 1024);
            xzv[2] = __ldcs(xp + 2048);
            xzv[3] = __ldcs(xp + 3072);
        }

        // wait for THIS warp's h sub-slice; then re-arm its expect for next phase.
        // (expect precedes our cluster-arrive, hence any remote TMA of next phase)
        mbar_wait(mb + kq8 * 8, (uint32_t)(s & 1));
        if (mtp == 0 && lane == 0 && s + 1 < TQ)
            mbar_expect(mb + kq8 * 8, 16384);

        float acc0[4][4], acc1[4][4];
        #pragma unroll
        for (int nt = 0; nt < 4; nt++)
            #pragma unroll
            for (int q = 0; q < 4; q++) { acc0[nt][q] = 0.f; acc1[nt][q] = 0.f; }

        #pragma unroll
        for (int i = 0; i < 8; i++) {
            const int kk = kb + i;
            uint4 A0 = hbuf[(kk * 4 + mt0) * 32 + lane];
            uint4 A1 = hbuf[(kk * 4 + mt1) * 32 + lane];
            #pragma unroll
            for (int nt = 0; nt < 4; nt++) {
                uint2 Bv = sWh[(kk * 4 + nt) * 32 + lane];
                mma16816h(acc0[nt], A0.x, A0.y, A0.z, A0.w, Bv.x, Bv.y);
                mma16816h(acc1[nt], A1.x, A1.y, A1.z, A1.w, Bv.x, Bv.y);
            }
        }
        cluster_arrive();   // this CTA is done reading hbuf for step s

        // stage K-eighth partials (fp16 pairs: (zi,zf),(zg,zo))
        {
            #pragma unroll
            for (int q = 0; q < 4; q++) {
                int roff = grp + ((q >> 1) << 3);
                int col  = 2 * tig + (q & 1);
                zsf16[kq8 * 512 + (mt0 * 16 + roff) * 8 + col] =
                    make_uint2(pack2h(acc0[0][q], acc0[1][q]), pack2h(acc0[2][q], acc0[3][q]));
                zsf16[kq8 * 512 + (mt1 * 16 + roff) * 8 + col] =
                    make_uint2(pack2h(acc1[0][q], acc1[1][q]), pack2h(acc1[2][q], acc1[3][q]));
            }
        }
        __syncthreads();

        // gates + state update + IMMEDIATE per-thread fp16 publish
        float nh, nc;
        const int row = tid >> 3, col = tid & 7;
        {
            float zi = xzv[0], zf = xzv[1], zg = xzv[2], zo = xzv[3];
            #pragma unroll
            for (int kz = 0; kz < 8; kz++) {
                uint2 v = zsf16[kz * 512 + tid];
                __half2 a = *reinterpret_cast<__half2*>(&v.x);
                __half2 b = *reinterpret_cast<__half2*>(&v.y);
                float2 fa = __half22float2(a), fb = __half22float2(b);
                zi += fa.x; zf += fa.y; zg += fb.x; zo += fb.y;
            }
            nc = sig_fast(zf) * creg + sig_fast(zi) * tanh_acc(zg);
            nh = sig_fast(zo) * tanh_acc(nc);
            creg = nc;
            // publish this element's fp16 h directly into the frag slot
            int mt2 = row >> 4, r16 = row & 15;
            int lane2 = (r16 & 7) * 4 + (col >> 1);
            int fidx = ((j & 1) << 1) | (r16 >> 3);
            __half hv = __float2half_rn(nh);
            char* dst = (char*)&g_hf[(s + 1) & 1][j >> 1][mt2][lane2]
                        + fidx * 4 + (col & 1) * 2;
            asm volatile("st.global.b16 [%0], %1;"
                         :: "l"(dst), "h"(__half_as_ushort(hv)) : "memory");
        }
        __threadfence();
        __syncthreads();
        if (tid == 0) atomicExch(&g_flag[j], s + 1);

        // out stores: OFF the inter-CTA critical path
        __stcs(&out[((size_t)row * TQ + s) * HQ + j * 8 + col], nh);
        if (s == TQ - 1) {
            __stcs(&out[OFF_C + (size_t)row * HQ + j * 8 + col], nc);
            __stcs(&out[OFF_H + (size_t)row * HQ + j * 8 + col], nh);
        }

        // SMEM hbuf safe to overwrite once all 4 cluster CTAs arrived (post-MMA)
        cluster_wait();

        // fetch h(s+1): warps 0,1 each gate their sub-slice on its 16 producers
        if (s + 1 < TQ && warp < 2) {
            const int sub = 2 * (int)rank + warp;
            if (lane < 16) {
                const int f = 16 * sub + lane;
                while (ld_acq(&g_flag[f]) < s + 1) __nanosleep(16);
            }
            __syncwarp();
            if (lane == 0) {
                const char* src = (const char*)&g_hf[(s + 1) & 1][0][0][0] + sub * 16384;
                tma_bulk_mc(hbase + sub * 16384, src, 16384, mb + sub * 8, MASK);
            }
        }
    }
}

// ---------------- launch: forked capture, phase1 overlaps the scan ----------------
extern "C" void kernel_launch(void* const* d_in, const int* in_sizes, int n_in,
                              void* d_out, int out_size)
{
    (void)in_sizes; (void)n_in; (void)out_size;
    const float* x  = (const float*)d_in[0];
    const float* h0 = (const float*)d_in[1];
    const float* c0 = (const float*)d_in[2];
    const float* Wi = (const float*)d_in[3];
    const float* Wh = (const float*)d_in[4];
    const float* b  = (const float*)d_in[5];
    float* out = (float*)d_out;

    float* xz_p = nullptr;
    cudaGetSymbolAddress((void**)&xz_p, g_xz);

    const int SCAN_SMEM = 229376 + 128;   // 229504 (sWh+hbuf+zsf16+mbarriers)

    static cudaStream_t s2 = nullptr;
    static cudaEvent_t evA = nullptr, evB = nullptr;
    static bool inited = false;
    if (!inited) {
        cudaStreamCreateWithFlags(&s2, cudaStreamNonBlocking);
        cudaEventCreateWithFlags(&evA, cudaEventDisableTiming);
        cudaEventCreateWithFlags(&evB, cudaEventDisableTiming);
        cudaFuncSetAttribute(scan_kernel, cudaFuncAttributeMaxDynamicSharedMemorySize, SCAN_SMEM);
        inited = true;
    }

    init_kernel<<<32, 256>>>(h0);

    // fork: phase-1 GEMM on s2, ordered after init
    cudaEventRecord(evA, 0);
    cudaStreamWaitEvent(s2, evA, 0);
    gemm_split_kernel<<<16384, 256, 0, s2>>>(x, Wi, b, xz_p, ZN, DQ);
    cudaEventRecord(evB, s2);

    // scan: cluster launch (32 clusters of 4) on the default stream
    {
        cudaLaunchConfig_t cfg = {};
        cfg.gridDim = dim3(NCTA, 1, 1);
        cfg.blockDim = dim3(512, 1, 1);
        cfg.dynamicSmemBytes = SCAN_SMEM;
        cfg.stream = 0;
        cudaLaunchAttribute attrs[1];
        attrs[0].id = cudaLaunchAttributeClusterDimension;
        attrs[0].val.clusterDim = {CLSZ, 1, 1};
        cfg.attrs = attrs;
        cfg.numAttrs = 1;
        cudaLaunchKernelEx(&cfg, scan_kernel, Wh, c0, out);
    }

    // join
    cudaStreamWaitEvent(0, evB, 0);
}

// round 17
// speedup vs baseline: 1.6479x; 1.0321x over previous
#include <cuda_runtime.h>
#include <cuda_bf16.h>
#include <cuda_fp16.h>
#include <cstdint>
#include <cstddef>

#define BQ 64
#define TQ 512
#define DQ 1024
#define HQ 1024
#define ZN 4096   // 4H
#define NCTA 128  // scan CTAs; CTA j owns h cols [8j, 8j+8)
#define CLSZ 4    // scan cluster size

// ---------------- scratch (allocation-free __device__ globals) ----------------
__device__ float g_xz[(size_t)BQ * TQ * ZN];          // 512 MB: x @ Wi + b
// h in MMA A-fragment order, fp16, SPLIT BY COLUMN-HALF so each producer CTA's
// publish region is one contiguous 1KB block:
// [buf][k16-chunk][half][m-tile][lane] = uint2 (.x = row-group 0, .y = row-group 1)
__device__ uint2 g_hf2[2][64][2][4][32];
__device__ int   g_flag[NCTA];
__device__ int   g_done[8];                            // phase-1 t-chunk completion

// ---------------- helpers ----------------
__device__ __forceinline__ void bsplit(float v, uint16_t& h, uint16_t& l) {
    __nv_bfloat16 bh = __float2bfloat16(v);
    __nv_bfloat16 bl = __float2bfloat16(v - __bfloat162float(bh));
    h = __bfloat16_as_ushort(bh);
    l = __bfloat16_as_ushort(bl);
}
__device__ __forceinline__ void pack2(float v0, float v1, uint32_t& hi, uint32_t& lo) {
    uint16_t h0, l0, h1, l1;
    bsplit(v0, h0, l0); bsplit(v1, h1, l1);
    hi = (uint32_t)h0 | ((uint32_t)h1 << 16);
    lo = (uint32_t)l0 | ((uint32_t)l1 << 16);
}
// fp16 pack of two floats
__device__ __forceinline__ uint32_t pack2h(float v0, float v1) {
    __half2 p = __floats2half2_rn(v0, v1);
    return *reinterpret_cast<uint32_t*>(&p);
}
// bf16 MMA (phase 1)
__device__ __forceinline__ void mma16816(float c[4], uint32_t a0, uint32_t a1,
                                         uint32_t a2, uint32_t a3,
                                         uint32_t b0, uint32_t b1) {
    asm volatile(
        "mma.sync.aligned.m16n8k16.row.col.f32.bf16.bf16.f32 "
        "{%0,%1,%2,%3},{%4,%5,%6,%7},{%8,%9},{%0,%1,%2,%3};"
        : "+f"(c[0]), "+f"(c[1]), "+f"(c[2]), "+f"(c[3])
        : "r"(a0), "r"(a1), "r"(a2), "r"(a3), "r"(b0), "r"(b1));
}
// fp16 MMA (scan)
__device__ __forceinline__ void mma16816h(float c[4], uint32_t a0, uint32_t a1,
                                          uint32_t a2, uint32_t a3,
                                          uint32_t b0, uint32_t b1) {
    asm volatile(
        "mma.sync.aligned.m16n8k16.row.col.f32.f16.f16.f32 "
        "{%0,%1,%2,%3},{%4,%5,%6,%7},{%8,%9},{%0,%1,%2,%3};"
        : "+f"(c[0]), "+f"(c[1]), "+f"(c[2]), "+f"(c[3])
        : "r"(a0), "r"(a1), "r"(a2), "r"(a3), "r"(b0), "r"(b1));
}
__device__ __forceinline__ int ld_acq(const int* p) {
    int v;
    asm volatile("ld.global.acquire.gpu.b32 %0,[%1];" : "=r"(v) : "l"(p) : "memory");
    return v;
}
// 1-MUFU approx sigmoid (abs err ~2.4e-4): 0.5 + 0.5*tanh.approx(x/2)
__device__ __forceinline__ float sig_fast(float x) {
    float y;
    asm("tanh.approx.f32 %0,%1;" : "=f"(y) : "f"(0.5f * x));
    return fmaf(0.5f, y, 0.5f);
}
// 2-MUFU accurate tanh (~1e-6): 2/(1+e^{-2x}) - 1
__device__ __forceinline__ float tanh_acc(float x) {
    float e = __expf(-2.0f * x);
    return __fdividef(2.0f, 1.0f + e) - 1.0f;
}
// ---- mbarrier / TMA / cluster primitives ----
__device__ __forceinline__ void mbar_init(uint32_t a, uint32_t cnt) {
    asm volatile("mbarrier.init.shared.b64 [%0], %1;" :: "r"(a), "r"(cnt) : "memory");
}
__device__ __forceinline__ void mbar_expect(uint32_t a, uint32_t tx) {
    asm volatile("mbarrier.arrive.expect_tx.shared.b64 _, [%0], %1;"
                 :: "r"(a), "r"(tx) : "memory");
}
__device__ __forceinline__ void mbar_wait(uint32_t a, uint32_t ph) {
    uint32_t done;
    asm volatile(
        "{\n\t.reg .pred p;\n\t"
        "mbarrier.try_wait.parity.acquire.cta.shared::cta.b64 p, [%1], %2;\n\t"
        "selp.b32 %0, 1, 0, p;\n\t}"
        : "=r"(done) : "r"(a), "r"(ph) : "memory");
    if (!done) {
        asm volatile(
            "{\n\t.reg .pred P1;\n"
            "WAIT_LOOP_%=:\n\t"
            "mbarrier.try_wait.parity.acquire.cta.shared::cta.b64 P1, [%0], %1, 0x989680;\n\t"
            "@P1 bra.uni WAIT_DONE_%=;\n\t"
            "bra.uni WAIT_LOOP_%=;\n"
            "WAIT_DONE_%=:\n\t}"
            :: "r"(a), "r"(ph) : "memory");
    }
}
__device__ __forceinline__ void tma_bulk_mc(uint32_t dst, const void* src,
                                            uint32_t bytes, uint32_t mbar, uint16_t mask) {
    asm volatile(
        "cp.async.bulk.shared::cluster.global.mbarrier::complete_tx::bytes"
        ".multicast::cluster [%0], [%1], %2, [%3], %4;"
        :: "r"(dst), "l"(src), "r"(bytes), "r"(mbar), "h"(mask) : "memory");
}
__device__ __forceinline__ void cluster_arrive() {
    asm volatile("barrier.cluster.arrive.aligned;" ::: "memory");
}
__device__ __forceinline__ void cluster_wait() {
    asm volatile("barrier.cluster.wait.aligned;" ::: "memory");
}
__device__ __forceinline__ uint32_t cl_rank() {
    uint32_t r;
    asm("mov.u32 %0, %%cluster_ctarank;" : "=r"(r));
    return r;
}

// ---------------- init: h0 -> fp16 frag buffer 0 (split layout), reset flags ----------------
__global__ __launch_bounds__(256) void init_kernel(const float* __restrict__ h0) {
    int u = blockIdx.x * 256 + threadIdx.x;          // 8192 = 64*4*32
    if (u < NCTA) g_flag[u] = 0;
    if (u < 8)    g_done[u] = 0;
    int lane = u & 31, mt = (u >> 5) & 3, kk = u >> 7;
    int grp = lane >> 2, tig = lane & 3;
    int r0 = mt * 16 + grp, r1 = r0 + 8;
    int k0 = kk * 16 + 2 * tig;
    float2 v00 = *(const float2*)&h0[(size_t)r0 * HQ + k0];
    float2 v10 = *(const float2*)&h0[(size_t)r1 * HQ + k0];
    float2 v01 = *(const float2*)&h0[(size_t)r0 * HQ + k0 + 8];
    float2 v11 = *(const float2*)&h0[(size_t)r1 * HQ + k0 + 8];
    g_hf2[0][kk][0][mt][lane] = make_uint2(pack2h(v00.x, v00.y), pack2h(v10.x, v10.y));
    g_hf2[0][kk][1][mt][lane] = make_uint2(pack2h(v01.x, v01.y), pack2h(v11.x, v11.y));
}

// ---------------- phase 1: xz = x @ Wi + b  (M=32768,N=4096,K=1024) ----------------
// 1-D grid ordered by t-chunk: id = tc*2048 + b*32 + n. CTA tile 64x128, BK=32.
// bf16 3-term split (unchanged — accuracy of xz preserved).
__global__ __launch_bounds__(256, 2) void gemm_split_kernel(
    const float* __restrict__ A, const float* __restrict__ Bm,
    const float* __restrict__ bias, float* __restrict__ C, int N, int K)
{
    __shared__ uint32_t AsH[64][20], AsL[64][20];
    __shared__ uint32_t BsH[16][136], BsL[16][136];

    const int tid  = threadIdx.x;
    const int lane = tid & 31, warp = tid >> 5;
    const int grp = lane >> 2, tig = lane & 3;
    const int wr = (warp >> 2) << 5;
    const int wc = (warp & 3) << 5;

    const int id  = blockIdx.x;
    const int tc  = id >> 11;            // t-chunk 0..7
    const int rem = id & 2047;
    const int bb  = rem >> 5, nn = rem & 31;
    const int mbase = (bb * 8 + tc) * 64;
    const int nbase = nn * 128;

    float acc[2][4][4];
    #pragma unroll
    for (int i = 0; i < 2; i++)
        #pragma unroll
        for (int j = 0; j < 4; j++)
            #pragma unroll
            for (int q = 0; q < 4; q++) acc[i][j][q] = 0.f;

    for (int k0 = 0; k0 < K; k0 += 32) {
        #pragma unroll
        for (int i = 0; i < 2; i++) {
            int idx = tid + i * 256;
            int r = idx >> 3, q = idx & 7;
            float4 v = *reinterpret_cast<const float4*>(&A[(size_t)(mbase + r) * K + k0 + q * 4]);
            pack2(v.x, v.y, AsH[r][q * 2],     AsL[r][q * 2]);
            pack2(v.z, v.w, AsH[r][q * 2 + 1], AsL[r][q * 2 + 1]);
        }
        #pragma unroll
        for (int i = 0; i < 2; i++) {
            int idx = tid + i * 256;
            int p = idx >> 5, ng = idx & 31;
            const float4 r0 = *reinterpret_cast<const float4*>(&Bm[(size_t)(k0 + 2 * p) * N + nbase + ng * 4]);
            const float4 r1 = *reinterpret_cast<const float4*>(&Bm[(size_t)(k0 + 2 * p + 1) * N + nbase + ng * 4]);
            pack2(r0.x, r1.x, BsH[p][ng * 4 + 0], BsL[p][ng * 4 + 0]);
            pack2(r0.y, r1.y, BsH[p][ng * 4 + 1], BsL[p][ng * 4 + 1]);
            pack2(r0.z, r1.z, BsH[p][ng * 4 + 2], BsL[p][ng * 4 + 2]);
            pack2(r0.w, r1.w, BsH[p][ng * 4 + 3], BsL[p][ng * 4 + 3]);
        }
        __syncthreads();

        #pragma unroll
        for (int kk = 0; kk < 2; kk++) {
            uint32_t aH[2][4], aL[2][4], bH[4][2], bL[4][2];
            #pragma unroll
            for (int mi = 0; mi < 2; mi++) {
                int r0 = wr + mi * 16 + grp, r1 = r0 + 8;
                int pq = kk * 8 + tig;
                aH[mi][0] = AsH[r0][pq];     aL[mi][0] = AsL[r0][pq];
                aH[mi][1] = AsH[r1][pq];     aL[mi][1] = AsL[r1][pq];
                aH[mi][2] = AsH[r0][pq + 4]; aL[mi][2] = AsL[r0][pq + 4];
                aH[mi][3] = AsH[r1][pq + 4]; aL[mi][3] = AsL[r1][pq + 4];
            }
            #pragma unroll
            for (int ni = 0; ni < 4; ni++) {
                int cc = wc + ni * 8 + grp;
                int p0 = kk * 8 + tig;
                bH[ni][0] = BsH[p0][cc];     bL[ni][0] = BsL[p0][cc];
                bH[ni][1] = BsH[p0 + 4][cc]; bL[ni][1] = BsL[p0 + 4][cc];
            }
            #pragma unroll
            for (int mi = 0; mi < 2; mi++)
                #pragma unroll
                for (int ni = 0; ni < 4; ni++) {
                    float* c = acc[mi][ni];
                    mma16816(c, aH[mi][0], aH[mi][1], aH[mi][2], aH[mi][3], bH[ni][0], bH[ni][1]);
                    mma16816(c, aH[mi][0], aH[mi][1], aH[mi][2], aH[mi][3], bL[ni][0], bL[ni][1]);
                    mma16816(c, aL[mi][0], aL[mi][1], aL[mi][2], aL[mi][3], bH[ni][0], bH[ni][1]);
                }
        }
        __syncthreads();
    }

    #pragma unroll
    for (int mi = 0; mi < 2; mi++) {
        int r0 = mbase + wr + mi * 16 + grp;
        #pragma unroll
        for (int ni = 0; ni < 4; ni++) {
            int c0 = nbase + wc + ni * 8 + tig * 2;
            float2 bv = *(const float2*)&bias[c0];
            __stcs((float2*)&C[(size_t)r0 * N + c0],
                   make_float2(acc[mi][ni][0] + bv.x, acc[mi][ni][1] + bv.y));
            __stcs((float2*)&C[(size_t)(r0 + 8) * N + c0],
                   make_float2(acc[mi][ni][2] + bv.x, acc[mi][ni][3] + bv.y));
        }
    }
    __threadfence();
    __syncthreads();
    if (tid == 0) atomicAdd(&g_done[tc], 1);
}

// ---------------- persistent scan kernel (clusters of 4 + sub-sliced TMA multicast) ----------------
// 128 CTAs x 512 thr (16 warps), 32 clusters of 4. Warp = (kq8 = warp>>1, mtp = warp&1).
// h layout split by column-half -> each CTA's publish is 256 dense 4B stores.
__global__ __launch_bounds__(512, 1) void scan_kernel(
    const float* __restrict__ Wh, const float* __restrict__ c0,
    float* __restrict__ out)
{
    extern __shared__ char smem[];
    uint2* sWh   = reinterpret_cast<uint2*>(smem);                    // [64][4][32] uint2 = 64KB
    uint2* hbuf2 = reinterpret_cast<uint2*>(smem + 65536);            // [64][2][4][32] uint2 = 128KB
    uint2* zsf16 = reinterpret_cast<uint2*>(smem + 196608);           // [8][512] uint2 = 32KB
    const uint32_t smem_u32 = [] (const void* p) {
        uint32_t a;
        asm("{ .reg .u64 t; cvta.to.shared.u64 t, %1; cvt.u32.u64 %0, t; }"
            : "=r"(a) : "l"(p));
        return a;
    }(smem);
    const uint32_t mb    = smem_u32 + 229376;   // 8 mbarriers (8B each)
    const uint32_t hbase = smem_u32 + 65536;    // hbuf shared addr

    const int j = blockIdx.x, tid = threadIdx.x;
    const int lane = tid & 31, warp = tid >> 5;
    const int grp = lane >> 2, tig = lane & 3;
    const int kq8 = warp >> 1;              // K-eighth 0..7
    const int mtp = warp & 1;               // m-tile pair 0..1
    const int mt0 = mtp * 2, mt1 = mt0 + 1;
    const int kb = kq8 * 8;
    const uint32_t rank = cl_rank();        // 0..3
    const uint16_t MASK = (1u << CLSZ) - 1u;
    // gate-thread mapping (tid < 256): 2 adjacent columns each
    const int grow = tid >> 2, gcp = tid & 3;

    // ---- one-time: Wh slice -> SMEM B-fragments (fp16) ----
    for (int it = 0; it < 16; it++) {
        int slot = tid + it * 512;                   // 8192 slots
        int sl = slot & 31, nt = (slot >> 5) & 3, kk = slot >> 7;
        int sg = sl >> 2, st_ = sl & 3;
        int col = nt * 1024 + j * 8 + sg;
        int k0 = kk * 16 + 2 * st_;
        float w0 = Wh[(size_t)k0 * ZN + col];
        float w1 = Wh[(size_t)(k0 + 1) * ZN + col];
        float w8 = Wh[(size_t)(k0 + 8) * ZN + col];
        float w9 = Wh[(size_t)(k0 + 9) * ZN + col];
        uint2 v;
        v.x = pack2h(w0, w1);
        v.y = pack2h(w8, w9);
        sWh[(kk * 4 + nt) * 32 + sl] = v;
    }
    // c state (2 elems/thread for tid < 256)
    float creg0 = 0.f, creg1 = 0.f;
    if (tid < 256) {
        float2 cv = *(const float2*)&c0[(size_t)grow * HQ + j * 8 + 2 * gcp];
        creg0 = cv.x; creg1 = cv.y;
    }
    // mbarriers + expects for phase 0
    if (tid == 0) {
        #pragma unroll
        for (int r = 0; r < 8; r++) mbar_init(mb + r * 8, 1);
        #pragma unroll
        for (int r = 0; r < 8; r++) mbar_expect(mb + r * 8, 16384);
    }
    __syncthreads();
    cluster_arrive();
    cluster_wait();
    // initial TMA: warps 0,1 fetch this rank's two sub-slices of h(0)
    if (warp < 2 && lane == 0) {
        const int sub = 2 * (int)rank + warp;
        const char* src = (const char*)&g_hf2[0][0][0][0][0] + sub * 16384;
        tma_bulk_mc(hbase + sub * 16384, src, 16384, mb + sub * 8, MASK);
    }

    const size_t OFF_C = (size_t)BQ * TQ * HQ;
    const size_t OFF_H = OFF_C + (size_t)BQ * HQ;

    for (int s = 0; s < TQ; s++) {
        // gate on phase-1 t-chunk availability
        if ((s & 63) == 0) {
            if (tid == 0) {
                while (ld_acq(&g_done[s >> 6]) < 2048) __nanosleep(128);
            }
            __syncthreads();
        }

        // prefetch xz (independent of h): 4 gate-pairs as float2
        float2 xza, xzb, xzc, xzd;
        if (tid < 256) {
            const float* xp = &g_xz[((size_t)grow * TQ + s) * ZN + j * 8 + 2 * gcp];
            xza = __ldcs((const float2*)xp);
            xzb = __ldcs((const float2*)(xp + 1024));
            xzc = __ldcs((const float2*)(xp + 2048));
            xzd = __ldcs((const float2*)(xp + 3072));
        }

        // wait for THIS warp's h sub-slice; re-arm its expect for next phase
        mbar_wait(mb + kq8 * 8, (uint32_t)(s & 1));
        if (mtp == 0 && lane == 0 && s + 1 < TQ)
            mbar_expect(mb + kq8 * 8, 16384);

        float acc0[4][4], acc1[4][4];
        #pragma unroll
        for (int nt = 0; nt < 4; nt++)
            #pragma unroll
            for (int q = 0; q < 4; q++) { acc0[nt][q] = 0.f; acc1[nt][q] = 0.f; }

        #pragma unroll
        for (int i = 0; i < 8; i++) {
            const int kk = kb + i;
            uint2 h00 = hbuf2[((kk * 2 + 0) * 4 + mt0) * 32 + lane];
            uint2 h01 = hbuf2[((kk * 2 + 1) * 4 + mt0) * 32 + lane];
            uint2 h10 = hbuf2[((kk * 2 + 0) * 4 + mt1) * 32 + lane];
            uint2 h11 = hbuf2[((kk * 2 + 1) * 4 + mt1) * 32 + lane];
            #pragma unroll
            for (int nt = 0; nt < 4; nt++) {
                uint2 Bv = sWh[(kk * 4 + nt) * 32 + lane];
                mma16816h(acc0[nt], h00.x, h00.y, h01.x, h01.y, Bv.x, Bv.y);
                mma16816h(acc1[nt], h10.x, h10.y, h11.x, h11.y, Bv.x, Bv.y);
            }
        }
        cluster_arrive();   // this CTA is done reading hbuf for step s

        // stage K-eighth partials (fp16 pairs: (zi,zf),(zg,zo))
        {
            #pragma unroll
            for (int q = 0; q < 4; q++) {
                int roff = grp + ((q >> 1) << 3);
                int col  = 2 * tig + (q & 1);
                zsf16[kq8 * 512 + (mt0 * 16 + roff) * 8 + col] =
                    make_uint2(pack2h(acc0[0][q], acc0[1][q]), pack2h(acc0[2][q], acc0[3][q]));
                zsf16[kq8 * 512 + (mt1 * 16 + roff) * 8 + col] =
                    make_uint2(pack2h(acc1[0][q], acc1[1][q]), pack2h(acc1[2][q], acc1[3][q]));
            }
        }
        __syncthreads();

        // gates (2 cols/thread) + dense 4B publish
        float nh0, nh1, nc0, nc1;
        if (tid < 256) {
            float zi0 = xza.x, zf0 = xzb.x, zg0 = xzc.x, zo0 = xzd.x;
            float zi1 = xza.y, zf1 = xzb.y, zg1 = xzc.y, zo1 = xzd.y;
            #pragma unroll
            for (int kz = 0; kz < 8; kz++) {
                uint4 v = *reinterpret_cast<const uint4*>(&zsf16[kz * 512 + grow * 8 + 2 * gcp]);
                float2 f;
                f = __half22float2(*reinterpret_cast<__half2*>(&v.x)); zi0 += f.x; zf0 += f.y;
                f = __half22float2(*reinterpret_cast<__half2*>(&v.y)); zg0 += f.x; zo0 += f.y;
                f = __half22float2(*reinterpret_cast<__half2*>(&v.z)); zi1 += f.x; zf1 += f.y;
                f = __half22float2(*reinterpret_cast<__half2*>(&v.w)); zg1 += f.x; zo1 += f.y;
            }
            nc0 = sig_fast(zf0) * creg0 + sig_fast(zi0) * tanh_acc(zg0);
            nh0 = sig_fast(zo0) * tanh_acc(nc0);
            nc1 = sig_fast(zf1) * creg1 + sig_fast(zi1) * tanh_acc(zg1);
            nh1 = sig_fast(zo1) * tanh_acc(nc1);
            creg0 = nc0; creg1 = nc1;
            // publish: one aligned 4B store into CTA's contiguous 1KB region
            int mt2 = grow >> 4;
            int lane2 = (grow & 7) * 4 + gcp;
            int word = (grow >> 3) & 1;
            uint32_t* dst = reinterpret_cast<uint32_t*>(
                &g_hf2[(s + 1) & 1][j >> 1][j & 1][mt2][lane2]);
            dst[word] = pack2h(nh0, nh1);
            __threadfence();
        }
        __syncthreads();
        if (tid == 0) atomicExch(&g_flag[j], s + 1);

        // out stores: OFF the inter-CTA critical path
        if (tid < 256) {
            __stcs((float2*)&out[((size_t)grow * TQ + s) * HQ + j * 8 + 2 * gcp],
                   make_float2(nh0, nh1));
            if (s == TQ - 1) {
                __stcs((float2*)&out[OFF_C + (size_t)grow * HQ + j * 8 + 2 * gcp],
                       make_float2(nc0, nc1));
                __stcs((float2*)&out[OFF_H + (size_t)grow * HQ + j * 8 + 2 * gcp],
                       make_float2(nh0, nh1));
            }
        }

        // SMEM hbuf safe to overwrite once all 4 cluster CTAs arrived (post-MMA)
        cluster_wait();

        // fetch h(s+1): warps 0,1 each gate their sub-slice on its 16 producers
        if (s + 1 < TQ && warp < 2) {
            const int sub = 2 * (int)rank + warp;
            if (lane < 16) {
                const int f = 16 * sub + lane;
                while (ld_acq(&g_flag[f]) < s + 1) __nanosleep(16);
            }
            __syncwarp();
            if (lane == 0) {
                const char* src = (const char*)&g_hf2[(s + 1) & 1][0][0][0][0] + sub * 16384;
                tma_bulk_mc(hbase + sub * 16384, src, 16384, mb + sub * 8, MASK);
            }
        }
    }
}

// ---------------- launch: forked capture, phase1 overlaps the scan ----------------
extern "C" void kernel_launch(void* const* d_in, const int* in_sizes, int n_in,
                              void* d_out, int out_size)
{
    (void)in_sizes; (void)n_in; (void)out_size;
    const float* x  = (const float*)d_in[0];
    const float* h0 = (const float*)d_in[1];
    const float* c0 = (const float*)d_in[2];
    const float* Wi = (const float*)d_in[3];
    const float* Wh = (const float*)d_in[4];
    const float* b  = (const float*)d_in[5];
    float* out = (float*)d_out;

    float* xz_p = nullptr;
    cudaGetSymbolAddress((void**)&xz_p, g_xz);

    const int SCAN_SMEM = 229376 + 128;   // 229504 (sWh+hbuf+zsf16+mbarriers)

    static cudaStream_t s2 = nullptr;
    static cudaEvent_t evA = nullptr, evB = nullptr;
    static bool inited = false;
    if (!inited) {
        cudaStreamCreateWithFlags(&s2, cudaStreamNonBlocking);
        cudaEventCreateWithFlags(&evA, cudaEventDisableTiming);
        cudaEventCreateWithFlags(&evB, cudaEventDisableTiming);
        cudaFuncSetAttribute(scan_kernel, cudaFuncAttributeMaxDynamicSharedMemorySize, SCAN_SMEM);
        inited = true;
    }

    init_kernel<<<32, 256>>>(h0);

    // fork: phase-1 GEMM on s2, ordered after init
    cudaEventRecord(evA, 0);
    cudaStreamWaitEvent(s2, evA, 0);
    gemm_split_kernel<<<16384, 256, 0, s2>>>(x, Wi, b, xz_p, ZN, DQ);
    cudaEventRecord(evB, s2);

    // scan: cluster launch (32 clusters of 4) on the default stream
    {
        cudaLaunchConfig_t cfg = {};
        cfg.gridDim = dim3(NCTA, 1, 1);
        cfg.blockDim = dim3(512, 1, 1);
        cfg.dynamicSmemBytes = SCAN_SMEM;
        cfg.stream = 0;
        cudaLaunchAttribute attrs[1];
        attrs[0].id = cudaLaunchAttributeClusterDimension;
        attrs[0].val.clusterDim = {CLSZ, 1, 1};
        cfg.attrs = attrs;
        cfg.numAttrs = 1;
        cudaLaunchKernelEx(&cfg, scan_kernel, Wh, c0, out);
    }

    // join
    cudaStreamWaitEvent(0, evB, 0);
}